// round 1
// baseline (speedup 1.0000x reference)
#include <cuda_runtime.h>
#include <cuda_bf16.h>
#include <math.h>

// Problem constants
#define BB 4
#define TT 2048
#define CC 256
#define HH 8
#define HS 32
#define LL 4
#define FFN 256
#define CLS_H 512
#define N_OUT 10
#define NTOK (BB*TT)          // 8192

// ---------------- scratch (device globals; no allocations allowed) ----------
__device__ float g_x   [NTOK*CC];    // residual stream
__device__ float g_h   [NTOK*CC];    // LN output / scratch
__device__ float g_qkv [NTOK*3*CC];  // packed q|k|v per token
__device__ float g_o   [NTOK*CC];    // attention output (heads concat)
__device__ float g_f   [NTOK*FFN];   // FFN hidden
__device__ float g_wqkv[CC*3*CC];    // repacked QKV weight [K=256, N=768]

// ---------------- embedding: x = tok_emb[idx] + pos_emb[t] ------------------
__global__ void embed_kernel(const int* __restrict__ idx,
                             const float* __restrict__ tok,
                             const float* __restrict__ pos) {
    int i = blockIdx.x;          // token 0..8191
    int c = threadIdx.x;         // 0..255
    int t = i & (TT - 1);
    g_x[(size_t)i * CC + c] = tok[(size_t)idx[i] * CC + c] + pos[(size_t)t * CC + c];
}

// ---------------- LayerNorm (one block of 256 threads per token) ------------
__global__ void ln_kernel(const float* __restrict__ x, float* __restrict__ y,
                          const float* __restrict__ g, const float* __restrict__ b) {
    int row = blockIdx.x;
    int c   = threadIdx.x;
    __shared__ float red1[8];
    __shared__ float red2[8];

    float v = x[(size_t)row * CC + c];

    // mean
    float s = v;
    #pragma unroll
    for (int o = 16; o > 0; o >>= 1) s += __shfl_xor_sync(0xffffffffu, s, o);
    if ((c & 31) == 0) red1[c >> 5] = s;
    __syncthreads();
    float tot = 0.f;
    #pragma unroll
    for (int i = 0; i < 8; i++) tot += red1[i];
    float mean = tot * (1.0f / CC);

    // variance
    float d  = v - mean;
    float s2 = d * d;
    #pragma unroll
    for (int o = 16; o > 0; o >>= 1) s2 += __shfl_xor_sync(0xffffffffu, s2, o);
    if ((c & 31) == 0) red2[c >> 5] = s2;
    __syncthreads();
    float tot2 = 0.f;
    #pragma unroll
    for (int i = 0; i < 8; i++) tot2 += red2[i];
    float var = tot2 * (1.0f / CC);

    y[(size_t)row * CC + c] = d * rsqrtf(var + 1e-5f) * g[c] + b[c];
}

// ---------------- repack Wq/Wk/Wv[layer] -> [256, 768] row-major ------------
// dst[c*768 + s*256 + h*32 + d] = Ws[l, h, c, d]
__global__ void repack_qkv_kernel(const float* __restrict__ Wq,
                                  const float* __restrict__ Wk,
                                  const float* __restrict__ Wv, int layer) {
    int i = blockIdx.x * 256 + threadIdx.x;   // 0 .. 3*8*256*32-1
    int d = i & 31;
    int c = (i >> 5) & 255;
    int h = (i >> 13) & 7;
    int s = i >> 16;                          // 0,1,2
    const float* W = (s == 0) ? Wq : (s == 1) ? Wk : Wv;
    float val = W[(size_t)layer * HH * CC * HS + (size_t)h * CC * HS + (size_t)c * HS + d];
    g_wqkv[(size_t)c * (3 * CC) + s * CC + h * HS + d] = val;
}

// ---------------- tiled SGEMM: C[M,N] = A[M,K] @ B[K,N] + epilogue ----------
// EPI: 0 = plain store, 2 = bias + residual, 3 = bias + relu
#define BM 64
#define BN 64
#define BKK 16
template <int EPI>
__global__ void sgemm_kernel(const float* __restrict__ A, const float* __restrict__ B,
                             float* __restrict__ C, const float* __restrict__ bias,
                             const float* __restrict__ res, int M, int N, int K) {
    __shared__ float As[BKK][BM];
    __shared__ float Bs[BKK][BN];
    int m0 = blockIdx.y * BM;
    int n0 = blockIdx.x * BN;
    int tid = threadIdx.x;
    int tx = tid & 15, ty = tid >> 4;     // 16 x 16 threads
    int aRow = tid >> 2;                   // 0..63
    int aCol = (tid & 3) * 4;              // 0,4,8,12
    int bRow = tid >> 4;                   // 0..15
    int bCol = (tid & 15) * 4;             // 0..60

    float acc[4][4];
    #pragma unroll
    for (int i = 0; i < 4; i++)
        #pragma unroll
        for (int j = 0; j < 4; j++) acc[i][j] = 0.f;

    for (int k0 = 0; k0 < K; k0 += BKK) {
        float4 av = *(const float4*)(A + (size_t)(m0 + aRow) * K + k0 + aCol);
        float4 bv = *(const float4*)(B + (size_t)(k0 + bRow) * N + n0 + bCol);
        As[aCol + 0][aRow] = av.x;
        As[aCol + 1][aRow] = av.y;
        As[aCol + 2][aRow] = av.z;
        As[aCol + 3][aRow] = av.w;
        *(float4*)&Bs[bRow][bCol] = bv;
        __syncthreads();
        #pragma unroll
        for (int k = 0; k < BKK; k++) {
            float ra[4], rb[4];
            #pragma unroll
            for (int i = 0; i < 4; i++) ra[i] = As[k][ty * 4 + i];
            #pragma unroll
            for (int j = 0; j < 4; j++) rb[j] = Bs[k][tx * 4 + j];
            #pragma unroll
            for (int i = 0; i < 4; i++)
                #pragma unroll
                for (int j = 0; j < 4; j++) acc[i][j] += ra[i] * rb[j];
        }
        __syncthreads();
    }

    #pragma unroll
    for (int i = 0; i < 4; i++) {
        int m = m0 + ty * 4 + i;
        #pragma unroll
        for (int j = 0; j < 4; j++) {
            int n = n0 + tx * 4 + j;
            float v = acc[i][j];
            if (EPI >= 2) v += bias[n];
            if (EPI == 2) v += res[(size_t)m * N + n];
            if (EPI == 3) v = fmaxf(v, 0.f);
            C[(size_t)m * N + n] = v;
        }
    }
}

// ---------------- flash-style attention ------------------------------------
// grid: (T/64, B*H); block 256 threads. qkv layout: token-major [8192, 768],
// sections q(0) k(256) v(512), head h at offset h*32.
__global__ void attn_kernel(void) {
    int bh = blockIdx.y;
    int b = bh >> 3, h = bh & 7;
    int t0 = blockIdx.x * 64;

    __shared__ float Qs[64][HS];
    __shared__ float Ks[64][HS];
    __shared__ float Vs[64][HS];
    __shared__ float Ps[64][64];

    int tid = threadIdx.x;
    int row = tid >> 2;       // 0..63 query row within tile
    int q4  = tid & 3;        // quad lane

    // load Q tile
    for (int i = tid; i < 64 * HS; i += 256) {
        int r = i >> 5, d = i & 31;
        Qs[r][d] = g_qkv[(size_t)(b * TT + t0 + r) * (3 * CC) + h * HS + d];
    }

    float acc[8];
    #pragma unroll
    for (int i = 0; i < 8; i++) acc[i] = 0.f;
    float m = -1e30f, l = 0.f;

    for (int j0 = 0; j0 < TT; j0 += 64) {
        __syncthreads();   // previous-iter Ps/Vs consumers done; Q loaded
        for (int i = tid; i < 64 * HS; i += 256) {
            int r = i >> 5, d = i & 31;
            size_t base = (size_t)(b * TT + j0 + r) * (3 * CC);
            Ks[r][d] = g_qkv[base + CC + h * HS + d];
            Vs[r][d] = g_qkv[base + 2 * CC + h * HS + d];
        }
        __syncthreads();

        // scores: this thread covers j = q4*16 .. q4*16+15 for its row
        float s[16];
        float cmax = -1e30f;
        #pragma unroll
        for (int jj = 0; jj < 16; jj++) {
            int j = q4 * 16 + jj;
            float a = 0.f;
            #pragma unroll
            for (int k = 0; k < HS; k++) a += Qs[row][k] * Ks[j][k];
            s[jj] = a * 0.0625f;   // scale = C^-0.5 = 1/16
            cmax = fmaxf(cmax, s[jj]);
        }
        cmax = fmaxf(cmax, __shfl_xor_sync(0xffffffffu, cmax, 1));
        cmax = fmaxf(cmax, __shfl_xor_sync(0xffffffffu, cmax, 2));
        float mnew  = fmaxf(m, cmax);
        float alpha = __expf(m - mnew);
        float psum = 0.f;
        #pragma unroll
        for (int jj = 0; jj < 16; jj++) {
            float p = __expf(s[jj] - mnew);
            Ps[row][q4 * 16 + jj] = p;
            psum += p;
        }
        psum += __shfl_xor_sync(0xffffffffu, psum, 1);
        psum += __shfl_xor_sync(0xffffffffu, psum, 2);
        l = l * alpha + psum;
        m = mnew;
        #pragma unroll
        for (int dd = 0; dd < 8; dd++) acc[dd] *= alpha;
        __syncthreads();   // Ps complete

        // PV: this thread owns dims d = q4*8 .. q4*8+7 of its row
        int d0 = q4 * 8;
        for (int j = 0; j < 64; j++) {
            float p = Ps[row][j];
            #pragma unroll
            for (int dd = 0; dd < 8; dd++) acc[dd] += p * Vs[j][d0 + dd];
        }
    }

    float inv = 1.0f / l;
    int d0 = q4 * 8;
    #pragma unroll
    for (int dd = 0; dd < 8; dd++)
        g_o[(size_t)(b * TT + t0 + row) * CC + h * HS + d0 + dd] = acc[dd] * inv;
}

// ---------------- classifier: mean pool -> fc -> relu -> fc -> softmax ------
__global__ void cls_kernel(const float* __restrict__ Wc1, const float* __restrict__ bc1,
                           const float* __restrict__ Wc2, const float* __restrict__ bc2,
                           float* __restrict__ out) {
    int b = blockIdx.x;
    int tid = threadIdx.x;    // 512 threads
    __shared__ float emb[CC];
    __shared__ float hid[CLS_H];
    __shared__ float lg[N_OUT];

    if (tid < CC) {
        float sum = 0.f;
        const float* base = g_h + (size_t)b * TT * CC + tid;
        for (int t = 0; t < TT; t++) sum += base[(size_t)t * CC];
        emb[tid] = sum * (1.0f / TT);
    }
    __syncthreads();

    {
        float sum = bc1[tid];
        for (int c = 0; c < CC; c++) sum += emb[c] * Wc1[(size_t)c * CLS_H + tid];
        hid[tid] = fmaxf(sum, 0.f);
    }
    __syncthreads();

    if (tid < N_OUT) {
        float sum = bc2[tid];
        for (int k = 0; k < CLS_H; k++) sum += hid[k] * Wc2[(size_t)k * N_OUT + tid];
        lg[tid] = sum;
    }
    __syncthreads();

    if (tid == 0) {
        float mx = lg[0];
        for (int j = 1; j < N_OUT; j++) mx = fmaxf(mx, lg[j]);
        float e[N_OUT], se = 0.f;
        for (int j = 0; j < N_OUT; j++) { e[j] = __expf(lg[j] - mx); se += e[j]; }
        float inv = 1.0f / se;
        for (int j = 0; j < N_OUT; j++) out[b * N_OUT + j] = e[j] * inv;
    }
}

// ---------------- launch ----------------------------------------------------
extern "C" void kernel_launch(void* const* d_in, const int* in_sizes, int n_in,
                              void* d_out, int out_size) {
    const int*   idx   = (const int*)  d_in[0];
    const float* tok   = (const float*)d_in[1];
    const float* pos   = (const float*)d_in[2];
    const float* Wq    = (const float*)d_in[3];
    const float* Wk    = (const float*)d_in[4];
    const float* Wv    = (const float*)d_in[5];
    const float* Wproj = (const float*)d_in[6];
    const float* bproj = (const float*)d_in[7];
    const float* ln1g  = (const float*)d_in[8];
    const float* ln1b  = (const float*)d_in[9];
    const float* ln2g  = (const float*)d_in[10];
    const float* ln2b  = (const float*)d_in[11];
    const float* W1    = (const float*)d_in[12];
    const float* b1    = (const float*)d_in[13];
    const float* W2    = (const float*)d_in[14];
    const float* b2    = (const float*)d_in[15];
    const float* lnfg  = (const float*)d_in[16];
    const float* lnfb  = (const float*)d_in[17];
    const float* Wc1   = (const float*)d_in[18];
    const float* bc1   = (const float*)d_in[19];
    const float* Wc2   = (const float*)d_in[20];
    const float* bc2   = (const float*)d_in[21];
    float* out = (float*)d_out;

    float *px, *ph, *pqkv, *po, *pf, *pwqkv;
    cudaGetSymbolAddress((void**)&px,    g_x);
    cudaGetSymbolAddress((void**)&ph,    g_h);
    cudaGetSymbolAddress((void**)&pqkv,  g_qkv);
    cudaGetSymbolAddress((void**)&po,    g_o);
    cudaGetSymbolAddress((void**)&pf,    g_f);
    cudaGetSymbolAddress((void**)&pwqkv, g_wqkv);

    embed_kernel<<<NTOK, CC>>>(idx, tok, pos);

    for (int l = 0; l < LL; l++) {
        // LN1
        ln_kernel<<<NTOK, CC>>>(px, ph, ln1g + l * CC, ln1b + l * CC);
        // repack QKV weights for this layer
        repack_qkv_kernel<<<(3 * HH * CC * HS) / 256, 256>>>(Wq, Wk, Wv, l);
        // QKV: [8192,256] @ [256,768]
        sgemm_kernel<0><<<dim3((3 * CC) / BN, NTOK / BM), 256>>>(
            ph, pwqkv, pqkv, nullptr, nullptr, NTOK, 3 * CC, CC);
        // attention
        attn_kernel<<<dim3(TT / 64, BB * HH), 256>>>();
        // proj + bias + residual -> x
        sgemm_kernel<2><<<dim3(CC / BN, NTOK / BM), 256>>>(
            po, Wproj + (size_t)l * CC * CC, px, bproj + l * CC, px, NTOK, CC, CC);
        // LN2
        ln_kernel<<<NTOK, CC>>>(px, ph, ln2g + l * CC, ln2b + l * CC);
        // FFN1: relu(h @ W1 + b1)
        sgemm_kernel<3><<<dim3(FFN / BN, NTOK / BM), 256>>>(
            ph, W1 + (size_t)l * CC * FFN, pf, b1 + l * FFN, nullptr, NTOK, FFN, CC);
        // FFN2: x += f @ W2 + b2
        sgemm_kernel<2><<<dim3(CC / BN, NTOK / BM), 256>>>(
            pf, W2 + (size_t)l * FFN * CC, px, b2 + l * CC, px, NTOK, CC, FFN);
    }

    // final LN -> g_h, then classifier
    ln_kernel<<<NTOK, CC>>>(px, ph, lnfg, lnfb);
    cls_kernel<<<BB, CLS_H>>>(Wc1, bc1, Wc2, bc2, out);
}

// round 2
// speedup vs baseline: 3.6659x; 3.6659x over previous
#include <cuda_runtime.h>
#include <cuda_bf16.h>
#include <math.h>

// Problem constants
#define BB 4
#define TT 2048
#define CC 256
#define HH 8
#define HS 32
#define LL 4
#define FFN 256
#define CLS_H 512
#define N_OUT 10
#define NTOK (BB*TT)          // 8192

// ---------------- scratch (device globals; no allocations allowed) ----------
__device__ float g_x   [NTOK*CC];    // residual stream
__device__ float g_h   [NTOK*CC];    // LN output / scratch
__device__ float g_qkv [NTOK*3*CC];  // packed q|k|v per token
__device__ float g_o   [NTOK*CC];    // attention output (heads concat)
__device__ float g_f   [NTOK*FFN];   // FFN hidden
__device__ float g_wqkv[CC*3*CC];    // repacked QKV weight [K=256, N=768]

// ---------------- embedding: x = tok_emb[idx] + pos_emb[t] ------------------
__global__ void embed_kernel(const int* __restrict__ idx,
                             const float* __restrict__ tok,
                             const float* __restrict__ pos) {
    int i = blockIdx.x;          // token 0..8191
    int c = threadIdx.x;         // 0..255
    int t = i & (TT - 1);
    g_x[(size_t)i * CC + c] = tok[(size_t)idx[i] * CC + c] + pos[(size_t)t * CC + c];
}

// ---------------- LayerNorm (one block of 256 threads per token) ------------
__global__ void ln_kernel(const float* __restrict__ x, float* __restrict__ y,
                          const float* __restrict__ g, const float* __restrict__ b) {
    int row = blockIdx.x;
    int c   = threadIdx.x;
    __shared__ float red1[8];
    __shared__ float red2[8];

    float v = x[(size_t)row * CC + c];

    float s = v;
    #pragma unroll
    for (int o = 16; o > 0; o >>= 1) s += __shfl_xor_sync(0xffffffffu, s, o);
    if ((c & 31) == 0) red1[c >> 5] = s;
    __syncthreads();
    float tot = 0.f;
    #pragma unroll
    for (int i = 0; i < 8; i++) tot += red1[i];
    float mean = tot * (1.0f / CC);

    float d  = v - mean;
    float s2 = d * d;
    #pragma unroll
    for (int o = 16; o > 0; o >>= 1) s2 += __shfl_xor_sync(0xffffffffu, s2, o);
    if ((c & 31) == 0) red2[c >> 5] = s2;
    __syncthreads();
    float tot2 = 0.f;
    #pragma unroll
    for (int i = 0; i < 8; i++) tot2 += red2[i];
    float var = tot2 * (1.0f / CC);

    y[(size_t)row * CC + c] = d * rsqrtf(var + 1e-5f) * g[c] + b[c];
}

// ---------------- repack Wq/Wk/Wv[layer] -> [256, 768] row-major ------------
__global__ void repack_qkv_kernel(const float* __restrict__ Wq,
                                  const float* __restrict__ Wk,
                                  const float* __restrict__ Wv, int layer) {
    int i = blockIdx.x * 256 + threadIdx.x;
    int d = i & 31;
    int c = (i >> 5) & 255;
    int h = (i >> 13) & 7;
    int s = i >> 16;
    const float* W = (s == 0) ? Wq : (s == 1) ? Wk : Wv;
    float val = W[(size_t)layer * HH * CC * HS + (size_t)h * CC * HS + (size_t)c * HS + d];
    g_wqkv[(size_t)c * (3 * CC) + s * CC + h * HS + d] = val;
}

// ---------------- tiled SGEMM: C[M,N] = A[M,K] @ B[K,N] + epilogue ----------
// EPI: 0 = plain store, 2 = bias + residual, 3 = bias + relu
#define GBM 128
#define GBN 64
#define GBK 16
template <int EPI>
__global__ void __launch_bounds__(256)
sgemm_kernel(const float* __restrict__ A, const float* __restrict__ B,
             float* __restrict__ C, const float* __restrict__ bias,
             const float* __restrict__ res, int M, int N, int K) {
    __shared__ float As[GBK][GBM];
    __shared__ float Bs[GBK][GBN];
    int m0 = blockIdx.y * GBM;
    int n0 = blockIdx.x * GBN;
    int tid = threadIdx.x;
    int tx = tid & 15;            // 0..15 -> 4 cols
    int ty = tid >> 4;            // 0..15 -> 8 rows

    float acc[8][4];
    #pragma unroll
    for (int i = 0; i < 8; i++)
        #pragma unroll
        for (int j = 0; j < 4; j++) acc[i][j] = 0.f;

    // A-tile load mapping: 512 float4 per k0-step; thread does idx tid, tid+256
    // idx i -> row = i>>2 (0..127), c4 = (i&3)*4
    int aRow0 = tid >> 2;                 // idx = tid
    int aC0   = (tid & 3) * 4;
    int aRow1 = (tid + 256) >> 2;
    int aC1   = aC0;                      // (tid+256)&3 == tid&3
    // B-tile: 256 float4; thread idx tid -> krow = tid>>4, col = (tid&15)*4
    int bK  = tid >> 4;
    int bC  = (tid & 15) * 4;

    for (int k0 = 0; k0 < K; k0 += GBK) {
        float4 a0 = *(const float4*)(A + (size_t)(m0 + aRow0) * K + k0 + aC0);
        float4 a1 = *(const float4*)(A + (size_t)(m0 + aRow1) * K + k0 + aC1);
        float4 bv = *(const float4*)(B + (size_t)(k0 + bK) * N + n0 + bC);
        As[aC0 + 0][aRow0] = a0.x;
        As[aC0 + 1][aRow0] = a0.y;
        As[aC0 + 2][aRow0] = a0.z;
        As[aC0 + 3][aRow0] = a0.w;
        As[aC1 + 0][aRow1] = a1.x;
        As[aC1 + 1][aRow1] = a1.y;
        As[aC1 + 2][aRow1] = a1.z;
        As[aC1 + 3][aRow1] = a1.w;
        *(float4*)&Bs[bK][bC] = bv;
        __syncthreads();
        #pragma unroll
        for (int k = 0; k < GBK; k++) {
            float4 ra0 = *(const float4*)&As[k][ty * 8];
            float4 ra1 = *(const float4*)&As[k][ty * 8 + 4];
            float4 rb  = *(const float4*)&Bs[k][tx * 4];
            float ra[8] = {ra0.x, ra0.y, ra0.z, ra0.w, ra1.x, ra1.y, ra1.z, ra1.w};
            float rbv[4] = {rb.x, rb.y, rb.z, rb.w};
            #pragma unroll
            for (int i = 0; i < 8; i++)
                #pragma unroll
                for (int j = 0; j < 4; j++) acc[i][j] += ra[i] * rbv[j];
        }
        __syncthreads();
    }

    #pragma unroll
    for (int i = 0; i < 8; i++) {
        int m = m0 + ty * 8 + i;
        #pragma unroll
        for (int j = 0; j < 4; j++) {
            int n = n0 + tx * 4 + j;
            float v = acc[i][j];
            if (EPI >= 2) v += bias[n];
            if (EPI == 2) v += res[(size_t)m * N + n];
            if (EPI == 3) v = fmaxf(v, 0.f);
            C[(size_t)m * N + n] = v;
        }
    }
}

// ---------------- flash-style attention (conflict-free, reg-resident Q) -----
// grid: (T/64, B*H); block 256 threads. Thread (row=tid>>2, q4=tid&3) owns
// query row `row` and key subset j = 4*jj + q4 (jj=0..15). Partial PV acc over
// all 32 dims, quad-reduced at the end.
__global__ void __launch_bounds__(256, 2) attn_kernel(void) {
    int bh = blockIdx.y;
    int b = bh >> 3, h = bh & 7;
    int t0 = blockIdx.x * 64;

    __shared__ float Ks[64][36];   // stride 36: conflict-free + float4-aligned
    __shared__ float Vs[64][36];

    int tid = threadIdx.x;
    int row = tid >> 2;
    int q4  = tid & 3;

    // Q row -> registers
    float q[HS];
    {
        const float* qp = g_qkv + (size_t)(b * TT + t0 + row) * (3 * CC) + h * HS;
        #pragma unroll
        for (int u = 0; u < 8; u++) {
            float4 v = *(const float4*)(qp + u * 4);
            q[u * 4 + 0] = v.x; q[u * 4 + 1] = v.y;
            q[u * 4 + 2] = v.z; q[u * 4 + 3] = v.w;
        }
    }

    float acc[HS];
    #pragma unroll
    for (int d = 0; d < HS; d++) acc[d] = 0.f;
    float m = -1e30f, l = 0.f;

    for (int j0 = 0; j0 < TT; j0 += 64) {
        __syncthreads();   // previous-iter consumers done
        // load K/V tile (each thread: 2 K float4 + 2 V float4)
        #pragma unroll
        for (int i = tid; i < 512; i += 256) {
            int r  = i >> 3;
            int d4 = (i & 7) * 4;
            size_t base = (size_t)(b * TT + j0 + r) * (3 * CC) + h * HS + d4;
            *(float4*)&Ks[r][d4] = *(const float4*)(g_qkv + base + CC);
            *(float4*)&Vs[r][d4] = *(const float4*)(g_qkv + base + 2 * CC);
        }
        __syncthreads();

        // scores for j = 4*jj + q4
        float s[16];
        float cmax = -1e30f;
        #pragma unroll
        for (int jj = 0; jj < 16; jj++) {
            int j = jj * 4 + q4;
            float a = 0.f;
            #pragma unroll
            for (int k4 = 0; k4 < 8; k4++) {
                float4 kv = *(const float4*)&Ks[j][k4 * 4];
                a += q[k4*4+0] * kv.x + q[k4*4+1] * kv.y
                   + q[k4*4+2] * kv.z + q[k4*4+3] * kv.w;
            }
            s[jj] = a * 0.0625f;        // scale = C^-0.5 = 1/16
            cmax = fmaxf(cmax, s[jj]);
        }
        cmax = fmaxf(cmax, __shfl_xor_sync(0xffffffffu, cmax, 1));
        cmax = fmaxf(cmax, __shfl_xor_sync(0xffffffffu, cmax, 2));
        float mnew  = fmaxf(m, cmax);
        float alpha = __expf(m - mnew);
        m = mnew;
        l *= alpha;
        #pragma unroll
        for (int d = 0; d < HS; d++) acc[d] *= alpha;

        #pragma unroll
        for (int jj = 0; jj < 16; jj++) {
            int j = jj * 4 + q4;
            float p = __expf(s[jj] - mnew);
            l += p;
            #pragma unroll
            for (int d4 = 0; d4 < 8; d4++) {
                float4 vv = *(const float4*)&Vs[j][d4 * 4];
                acc[d4*4+0] += p * vv.x;
                acc[d4*4+1] += p * vv.y;
                acc[d4*4+2] += p * vv.z;
                acc[d4*4+3] += p * vv.w;
            }
        }
    }

    // quad reduce (lanes differing in bits 0,1 share a query row)
    #pragma unroll
    for (int d = 0; d < HS; d++) {
        acc[d] += __shfl_xor_sync(0xffffffffu, acc[d], 1);
        acc[d] += __shfl_xor_sync(0xffffffffu, acc[d], 2);
    }
    l += __shfl_xor_sync(0xffffffffu, l, 1);
    l += __shfl_xor_sync(0xffffffffu, l, 2);
    float inv = 1.0f / l;

    float* op = g_o + (size_t)(b * TT + t0 + row) * CC + h * HS + q4 * 8;
    #pragma unroll
    for (int d = 0; d < 8; d++) op[d] = acc[q4 * 8 + d] * inv;
}

// ---------------- classifier: mean pool -> fc -> relu -> fc -> softmax ------
__global__ void cls_kernel(const float* __restrict__ Wc1, const float* __restrict__ bc1,
                           const float* __restrict__ Wc2, const float* __restrict__ bc2,
                           float* __restrict__ out) {
    int b = blockIdx.x;
    int tid = threadIdx.x;    // 512 threads
    __shared__ float emb[CC];
    __shared__ float hid[CLS_H];
    __shared__ float lg[N_OUT];

    if (tid < CC) {
        float sum = 0.f;
        const float* base = g_h + (size_t)b * TT * CC + tid;
        for (int t = 0; t < TT; t++) sum += base[(size_t)t * CC];
        emb[tid] = sum * (1.0f / TT);
    }
    __syncthreads();

    {
        float sum = bc1[tid];
        for (int c = 0; c < CC; c++) sum += emb[c] * Wc1[(size_t)c * CLS_H + tid];
        hid[tid] = fmaxf(sum, 0.f);
    }
    __syncthreads();

    if (tid < N_OUT) {
        float sum = bc2[tid];
        for (int k = 0; k < CLS_H; k++) sum += hid[k] * Wc2[(size_t)k * N_OUT + tid];
        lg[tid] = sum;
    }
    __syncthreads();

    if (tid == 0) {
        float mx = lg[0];
        for (int j = 1; j < N_OUT; j++) mx = fmaxf(mx, lg[j]);
        float e[N_OUT], se = 0.f;
        for (int j = 0; j < N_OUT; j++) { e[j] = __expf(lg[j] - mx); se += e[j]; }
        float inv = 1.0f / se;
        for (int j = 0; j < N_OUT; j++) out[b * N_OUT + j] = e[j] * inv;
    }
}

// ---------------- launch ----------------------------------------------------
extern "C" void kernel_launch(void* const* d_in, const int* in_sizes, int n_in,
                              void* d_out, int out_size) {
    const int*   idx   = (const int*)  d_in[0];
    const float* tok   = (const float*)d_in[1];
    const float* pos   = (const float*)d_in[2];
    const float* Wq    = (const float*)d_in[3];
    const float* Wk    = (const float*)d_in[4];
    const float* Wv    = (const float*)d_in[5];
    const float* Wproj = (const float*)d_in[6];
    const float* bproj = (const float*)d_in[7];
    const float* ln1g  = (const float*)d_in[8];
    const float* ln1b  = (const float*)d_in[9];
    const float* ln2g  = (const float*)d_in[10];
    const float* ln2b  = (const float*)d_in[11];
    const float* W1    = (const float*)d_in[12];
    const float* b1    = (const float*)d_in[13];
    const float* W2    = (const float*)d_in[14];
    const float* b2    = (const float*)d_in[15];
    const float* lnfg  = (const float*)d_in[16];
    const float* lnfb  = (const float*)d_in[17];
    const float* Wc1   = (const float*)d_in[18];
    const float* bc1   = (const float*)d_in[19];
    const float* Wc2   = (const float*)d_in[20];
    const float* bc2   = (const float*)d_in[21];
    float* out = (float*)d_out;

    float *px, *ph, *pqkv, *po, *pf, *pwqkv;
    cudaGetSymbolAddress((void**)&px,    g_x);
    cudaGetSymbolAddress((void**)&ph,    g_h);
    cudaGetSymbolAddress((void**)&pqkv,  g_qkv);
    cudaGetSymbolAddress((void**)&po,    g_o);
    cudaGetSymbolAddress((void**)&pf,    g_f);
    cudaGetSymbolAddress((void**)&pwqkv, g_wqkv);

    embed_kernel<<<NTOK, CC>>>(idx, tok, pos);

    for (int l = 0; l < LL; l++) {
        ln_kernel<<<NTOK, CC>>>(px, ph, ln1g + l * CC, ln1b + l * CC);
        repack_qkv_kernel<<<(3 * HH * CC * HS) / 256, 256>>>(Wq, Wk, Wv, l);
        // QKV: [8192,256] @ [256,768]
        sgemm_kernel<0><<<dim3((3 * CC) / GBN, NTOK / GBM), 256>>>(
            ph, pwqkv, pqkv, nullptr, nullptr, NTOK, 3 * CC, CC);
        attn_kernel<<<dim3(TT / 64, BB * HH), 256>>>();
        // proj + bias + residual -> x
        sgemm_kernel<2><<<dim3(CC / GBN, NTOK / GBM), 256>>>(
            po, Wproj + (size_t)l * CC * CC, px, bproj + l * CC, px, NTOK, CC, CC);
        ln_kernel<<<NTOK, CC>>>(px, ph, ln2g + l * CC, ln2b + l * CC);
        // FFN1: relu(h @ W1 + b1)
        sgemm_kernel<3><<<dim3(FFN / GBN, NTOK / GBM), 256>>>(
            ph, W1 + (size_t)l * CC * FFN, pf, b1 + l * FFN, nullptr, NTOK, FFN, CC);
        // FFN2: x += f @ W2 + b2
        sgemm_kernel<2><<<dim3(CC / GBN, NTOK / GBM), 256>>>(
            pf, W2 + (size_t)l * FFN * CC, px, b2 + l * CC, px, NTOK, CC, FFN);
    }

    ln_kernel<<<NTOK, CC>>>(px, ph, lnfg, lnfb);
    cls_kernel<<<BB, CLS_H>>>(Wc1, bc1, Wc2, bc2, out);
}

// round 3
// speedup vs baseline: 5.4095x; 1.4756x over previous
#include <cuda_runtime.h>
#include <cuda_bf16.h>
#include <math.h>

// Problem constants
#define BB 4
#define TT 2048
#define CC 256
#define HH 8
#define HS 32
#define LL 4
#define FFN 256
#define CLS_H 512
#define N_OUT 10
#define NTOK (BB*TT)          // 8192

// ---------------- scratch (device globals; no allocations allowed) ----------
__device__ float g_x   [NTOK*CC];    // residual stream
__device__ float g_h   [NTOK*CC];    // LN output / scratch
__device__ float g_qkv [NTOK*3*CC];  // packed q|k|v per token
__device__ float g_o   [NTOK*CC];    // attention output (heads concat)
__device__ float g_f   [NTOK*FFN];   // FFN hidden
__device__ float g_wqkv[CC*3*CC];    // repacked QKV weight [K=256, N=768]

// ---------------- embedding: x = tok_emb[idx] + pos_emb[t] ------------------
__global__ void embed_kernel(const int* __restrict__ idx,
                             const float* __restrict__ tok,
                             const float* __restrict__ pos) {
    int i = blockIdx.x;
    int c = threadIdx.x;
    int t = i & (TT - 1);
    g_x[(size_t)i * CC + c] = tok[(size_t)idx[i] * CC + c] + pos[(size_t)t * CC + c];
}

// ---------------- LayerNorm (one block of 256 threads per token) ------------
__global__ void ln_kernel(const float* __restrict__ x, float* __restrict__ y,
                          const float* __restrict__ g, const float* __restrict__ b) {
    int row = blockIdx.x;
    int c   = threadIdx.x;
    __shared__ float red1[8];
    __shared__ float red2[8];

    float v = x[(size_t)row * CC + c];

    float s = v;
    #pragma unroll
    for (int o = 16; o > 0; o >>= 1) s += __shfl_xor_sync(0xffffffffu, s, o);
    if ((c & 31) == 0) red1[c >> 5] = s;
    __syncthreads();
    float tot = 0.f;
    #pragma unroll
    for (int i = 0; i < 8; i++) tot += red1[i];
    float mean = tot * (1.0f / CC);

    float d  = v - mean;
    float s2 = d * d;
    #pragma unroll
    for (int o = 16; o > 0; o >>= 1) s2 += __shfl_xor_sync(0xffffffffu, s2, o);
    if ((c & 31) == 0) red2[c >> 5] = s2;
    __syncthreads();
    float tot2 = 0.f;
    #pragma unroll
    for (int i = 0; i < 8; i++) tot2 += red2[i];
    float var = tot2 * (1.0f / CC);

    y[(size_t)row * CC + c] = d * rsqrtf(var + 1e-5f) * g[c] + b[c];
}

// ---------------- repack Wq/Wk/Wv[layer] -> [256, 768] row-major ------------
__global__ void repack_qkv_kernel(const float* __restrict__ Wq,
                                  const float* __restrict__ Wk,
                                  const float* __restrict__ Wv, int layer) {
    int i = blockIdx.x * 256 + threadIdx.x;
    int d = i & 31;
    int c = (i >> 5) & 255;
    int h = (i >> 13) & 7;
    int s = i >> 16;
    const float* W = (s == 0) ? Wq : (s == 1) ? Wk : Wv;
    float val = W[(size_t)layer * HH * CC * HS + (size_t)h * CC * HS + (size_t)c * HS + d];
    g_wqkv[(size_t)c * (3 * CC) + s * CC + h * HS + d] = val;
}

// ---------------- tiled SGEMM: C[M,N] = A[M,K] @ B[K,N] + epilogue ----------
// EPI: 0 = plain store, 2 = bias + residual, 3 = bias + relu
#define GBM 128
#define GBN 64
#define GBK 16
template <int EPI>
__global__ void __launch_bounds__(256)
sgemm_kernel(const float* __restrict__ A, const float* __restrict__ B,
             float* __restrict__ C, const float* __restrict__ bias,
             const float* __restrict__ res, int M, int N, int K) {
    __shared__ float As[GBK][GBM];
    __shared__ float Bs[GBK][GBN];
    int m0 = blockIdx.y * GBM;
    int n0 = blockIdx.x * GBN;
    int tid = threadIdx.x;
    int tx = tid & 15;
    int ty = tid >> 4;

    float acc[8][4];
    #pragma unroll
    for (int i = 0; i < 8; i++)
        #pragma unroll
        for (int j = 0; j < 4; j++) acc[i][j] = 0.f;

    int aRow0 = tid >> 2;
    int aC0   = (tid & 3) * 4;
    int aRow1 = (tid + 256) >> 2;
    int aC1   = aC0;
    int bK  = tid >> 4;
    int bC  = (tid & 15) * 4;

    for (int k0 = 0; k0 < K; k0 += GBK) {
        float4 a0 = *(const float4*)(A + (size_t)(m0 + aRow0) * K + k0 + aC0);
        float4 a1 = *(const float4*)(A + (size_t)(m0 + aRow1) * K + k0 + aC1);
        float4 bv = *(const float4*)(B + (size_t)(k0 + bK) * N + n0 + bC);
        As[aC0 + 0][aRow0] = a0.x;
        As[aC0 + 1][aRow0] = a0.y;
        As[aC0 + 2][aRow0] = a0.z;
        As[aC0 + 3][aRow0] = a0.w;
        As[aC1 + 0][aRow1] = a1.x;
        As[aC1 + 1][aRow1] = a1.y;
        As[aC1 + 2][aRow1] = a1.z;
        As[aC1 + 3][aRow1] = a1.w;
        *(float4*)&Bs[bK][bC] = bv;
        __syncthreads();
        #pragma unroll
        for (int k = 0; k < GBK; k++) {
            float4 ra0 = *(const float4*)&As[k][ty * 8];
            float4 ra1 = *(const float4*)&As[k][ty * 8 + 4];
            float4 rb  = *(const float4*)&Bs[k][tx * 4];
            float ra[8] = {ra0.x, ra0.y, ra0.z, ra0.w, ra1.x, ra1.y, ra1.z, ra1.w};
            float rbv[4] = {rb.x, rb.y, rb.z, rb.w};
            #pragma unroll
            for (int i = 0; i < 8; i++)
                #pragma unroll
                for (int j = 0; j < 4; j++) acc[i][j] += ra[i] * rbv[j];
        }
        __syncthreads();
    }

    #pragma unroll
    for (int i = 0; i < 8; i++) {
        int m = m0 + ty * 8 + i;
        #pragma unroll
        for (int j = 0; j < 4; j++) {
            int n = n0 + tx * 4 + j;
            float v = acc[i][j];
            if (EPI >= 2) v += bias[n];
            if (EPI == 2) v += res[(size_t)m * N + n];
            if (EPI == 3) v = fmaxf(v, 0.f);
            C[(size_t)m * N + n] = v;
        }
    }
}

// ---------------- flash-style attention, 2 query rows per thread -------------
// grid: (T/64, B*H); block 128 threads. Thread (rp=tid>>2, q4=tid&3) owns
// query rows 2*rp, 2*rp+1 and key subset j = 4*jj + q4 (jj=0..15). Each K/V
// row loaded from smem is reused for both rows (FMA/LDS ratio 8).
__global__ void __launch_bounds__(128, 2) attn_kernel(void) {
    int bh = blockIdx.y;
    int b = bh >> 3, h = bh & 7;
    int t0 = blockIdx.x * 64;

    __shared__ float Ks[64][36];   // stride 36: conflict-free + float4-aligned
    __shared__ float Vs[64][36];

    int tid = threadIdx.x;
    int rp = tid >> 2;
    int q4 = tid & 3;
    int r0 = rp * 2, r1 = r0 + 1;

    float q0[HS], q1[HS];
    {
        const float* qp0 = g_qkv + (size_t)(b * TT + t0 + r0) * (3 * CC) + h * HS;
        const float* qp1 = g_qkv + (size_t)(b * TT + t0 + r1) * (3 * CC) + h * HS;
        #pragma unroll
        for (int u = 0; u < 8; u++) {
            float4 v0 = *(const float4*)(qp0 + u * 4);
            float4 v1 = *(const float4*)(qp1 + u * 4);
            q0[u*4+0] = v0.x; q0[u*4+1] = v0.y; q0[u*4+2] = v0.z; q0[u*4+3] = v0.w;
            q1[u*4+0] = v1.x; q1[u*4+1] = v1.y; q1[u*4+2] = v1.z; q1[u*4+3] = v1.w;
        }
    }

    float acc0[HS], acc1[HS];
    #pragma unroll
    for (int d = 0; d < HS; d++) { acc0[d] = 0.f; acc1[d] = 0.f; }
    float m0 = -1e30f, m1 = -1e30f, l0 = 0.f, l1 = 0.f;

    for (int j0 = 0; j0 < TT; j0 += 64) {
        __syncthreads();
        // load K/V tile: 512 float4 each, 128 threads -> 4 each
        #pragma unroll
        for (int i = tid; i < 512; i += 128) {
            int r  = i >> 3;
            int d4 = (i & 7) * 4;
            size_t base = (size_t)(b * TT + j0 + r) * (3 * CC) + h * HS + d4;
            *(float4*)&Ks[r][d4] = *(const float4*)(g_qkv + base + CC);
            *(float4*)&Vs[r][d4] = *(const float4*)(g_qkv + base + 2 * CC);
        }
        __syncthreads();

        float s0[16], s1[16];
        float cm0 = -1e30f, cm1 = -1e30f;
        #pragma unroll
        for (int jj = 0; jj < 16; jj++) {
            int j = jj * 4 + q4;
            float a0 = 0.f, a1 = 0.f;
            #pragma unroll
            for (int k4 = 0; k4 < 8; k4++) {
                float4 kv = *(const float4*)&Ks[j][k4 * 4];
                a0 += q0[k4*4+0]*kv.x + q0[k4*4+1]*kv.y + q0[k4*4+2]*kv.z + q0[k4*4+3]*kv.w;
                a1 += q1[k4*4+0]*kv.x + q1[k4*4+1]*kv.y + q1[k4*4+2]*kv.z + q1[k4*4+3]*kv.w;
            }
            s0[jj] = a0 * 0.0625f;      // scale = C^-0.5 = 1/16
            s1[jj] = a1 * 0.0625f;
            cm0 = fmaxf(cm0, s0[jj]);
            cm1 = fmaxf(cm1, s1[jj]);
        }
        // reduce max across the 4 quad lanes (same row pair)
        cm0 = fmaxf(cm0, __shfl_xor_sync(0xffffffffu, cm0, 1));
        cm0 = fmaxf(cm0, __shfl_xor_sync(0xffffffffu, cm0, 2));
        cm1 = fmaxf(cm1, __shfl_xor_sync(0xffffffffu, cm1, 1));
        cm1 = fmaxf(cm1, __shfl_xor_sync(0xffffffffu, cm1, 2));
        float mn0 = fmaxf(m0, cm0);
        float mn1 = fmaxf(m1, cm1);
        float al0 = __expf(m0 - mn0);
        float al1 = __expf(m1 - mn1);
        m0 = mn0; m1 = mn1;
        l0 *= al0; l1 *= al1;
        #pragma unroll
        for (int d = 0; d < HS; d++) { acc0[d] *= al0; acc1[d] *= al1; }

        #pragma unroll
        for (int jj = 0; jj < 16; jj++) {
            int j = jj * 4 + q4;
            float p0 = __expf(s0[jj] - mn0);
            float p1 = __expf(s1[jj] - mn1);
            l0 += p0; l1 += p1;
            #pragma unroll
            for (int d4 = 0; d4 < 8; d4++) {
                float4 vv = *(const float4*)&Vs[j][d4 * 4];
                acc0[d4*4+0] += p0 * vv.x;  acc1[d4*4+0] += p1 * vv.x;
                acc0[d4*4+1] += p0 * vv.y;  acc1[d4*4+1] += p1 * vv.y;
                acc0[d4*4+2] += p0 * vv.z;  acc1[d4*4+2] += p1 * vv.z;
                acc0[d4*4+3] += p0 * vv.w;  acc1[d4*4+3] += p1 * vv.w;
            }
        }
    }

    // quad reduce (lanes differing in bits 0,1 share the row pair)
    #pragma unroll
    for (int d = 0; d < HS; d++) {
        acc0[d] += __shfl_xor_sync(0xffffffffu, acc0[d], 1);
        acc0[d] += __shfl_xor_sync(0xffffffffu, acc0[d], 2);
        acc1[d] += __shfl_xor_sync(0xffffffffu, acc1[d], 1);
        acc1[d] += __shfl_xor_sync(0xffffffffu, acc1[d], 2);
    }
    l0 += __shfl_xor_sync(0xffffffffu, l0, 1);
    l0 += __shfl_xor_sync(0xffffffffu, l0, 2);
    l1 += __shfl_xor_sync(0xffffffffu, l1, 1);
    l1 += __shfl_xor_sync(0xffffffffu, l1, 2);
    float inv0 = 1.0f / l0;
    float inv1 = 1.0f / l1;

    float* op0 = g_o + (size_t)(b * TT + t0 + r0) * CC + h * HS + q4 * 8;
    float* op1 = g_o + (size_t)(b * TT + t0 + r1) * CC + h * HS + q4 * 8;
    #pragma unroll
    for (int d = 0; d < 8; d++) {
        op0[d] = acc0[q4 * 8 + d] * inv0;
        op1[d] = acc1[q4 * 8 + d] * inv1;
    }
}

// ---------------- classifier: mean pool -> fc -> relu -> fc -> softmax ------
__global__ void __launch_bounds__(1024) cls_kernel(
        const float* __restrict__ Wc1, const float* __restrict__ bc1,
        const float* __restrict__ Wc2, const float* __restrict__ bc2,
        float* __restrict__ out) {
    int b = blockIdx.x;
    int tid = threadIdx.x;    // 1024 threads
    __shared__ float emb4[4][CC];
    __shared__ float emb[CC];
    __shared__ float hid[CLS_H];
    __shared__ float lg[N_OUT];

    {
        int c   = tid & 255;
        int qtr = tid >> 8;          // 0..3, each sums 512 t-rows
        float sum = 0.f;
        const float* base = g_h + (size_t)b * TT * CC + (size_t)qtr * 512 * CC + c;
        for (int t = 0; t < 512; t++) sum += base[(size_t)t * CC];
        emb4[qtr][c] = sum;
    }
    __syncthreads();
    if (tid < CC) {
        emb[tid] = (emb4[0][tid] + emb4[1][tid] + emb4[2][tid] + emb4[3][tid]) * (1.0f / TT);
    }
    __syncthreads();

    if (tid < CLS_H) {
        float sum = bc1[tid];
        for (int c = 0; c < CC; c++) sum += emb[c] * Wc1[(size_t)c * CLS_H + tid];
        hid[tid] = fmaxf(sum, 0.f);
    }
    __syncthreads();

    if (tid < N_OUT) {
        float sum = bc2[tid];
        for (int k = 0; k < CLS_H; k++) sum += hid[k] * Wc2[(size_t)k * N_OUT + tid];
        lg[tid] = sum;
    }
    __syncthreads();

    if (tid == 0) {
        float mx = lg[0];
        for (int j = 1; j < N_OUT; j++) mx = fmaxf(mx, lg[j]);
        float e[N_OUT], se = 0.f;
        for (int j = 0; j < N_OUT; j++) { e[j] = __expf(lg[j] - mx); se += e[j]; }
        float inv = 1.0f / se;
        for (int j = 0; j < N_OUT; j++) out[b * N_OUT + j] = e[j] * inv;
    }
}

// ---------------- launch ----------------------------------------------------
extern "C" void kernel_launch(void* const* d_in, const int* in_sizes, int n_in,
                              void* d_out, int out_size) {
    const int*   idx   = (const int*)  d_in[0];
    const float* tok   = (const float*)d_in[1];
    const float* pos   = (const float*)d_in[2];
    const float* Wq    = (const float*)d_in[3];
    const float* Wk    = (const float*)d_in[4];
    const float* Wv    = (const float*)d_in[5];
    const float* Wproj = (const float*)d_in[6];
    const float* bproj = (const float*)d_in[7];
    const float* ln1g  = (const float*)d_in[8];
    const float* ln1b  = (const float*)d_in[9];
    const float* ln2g  = (const float*)d_in[10];
    const float* ln2b  = (const float*)d_in[11];
    const float* W1    = (const float*)d_in[12];
    const float* b1    = (const float*)d_in[13];
    const float* W2    = (const float*)d_in[14];
    const float* b2    = (const float*)d_in[15];
    const float* lnfg  = (const float*)d_in[16];
    const float* lnfb  = (const float*)d_in[17];
    const float* Wc1   = (const float*)d_in[18];
    const float* bc1   = (const float*)d_in[19];
    const float* Wc2   = (const float*)d_in[20];
    const float* bc2   = (const float*)d_in[21];
    float* out = (float*)d_out;

    float *px, *ph, *pqkv, *po, *pf, *pwqkv;
    cudaGetSymbolAddress((void**)&px,    g_x);
    cudaGetSymbolAddress((void**)&ph,    g_h);
    cudaGetSymbolAddress((void**)&pqkv,  g_qkv);
    cudaGetSymbolAddress((void**)&po,    g_o);
    cudaGetSymbolAddress((void**)&pf,    g_f);
    cudaGetSymbolAddress((void**)&pwqkv, g_wqkv);

    embed_kernel<<<NTOK, CC>>>(idx, tok, pos);

    for (int l = 0; l < LL; l++) {
        ln_kernel<<<NTOK, CC>>>(px, ph, ln1g + l * CC, ln1b + l * CC);
        repack_qkv_kernel<<<(3 * HH * CC * HS) / 256, 256>>>(Wq, Wk, Wv, l);
        // QKV: [8192,256] @ [256,768]
        sgemm_kernel<0><<<dim3((3 * CC) / GBN, NTOK / GBM), 256>>>(
            ph, pwqkv, pqkv, nullptr, nullptr, NTOK, 3 * CC, CC);
        attn_kernel<<<dim3(TT / 64, BB * HH), 128>>>();
        // proj + bias + residual -> x
        sgemm_kernel<2><<<dim3(CC / GBN, NTOK / GBM), 256>>>(
            po, Wproj + (size_t)l * CC * CC, px, bproj + l * CC, px, NTOK, CC, CC);
        ln_kernel<<<NTOK, CC>>>(px, ph, ln2g + l * CC, ln2b + l * CC);
        // FFN1: relu(h @ W1 + b1)
        sgemm_kernel<3><<<dim3(FFN / GBN, NTOK / GBM), 256>>>(
            ph, W1 + (size_t)l * CC * FFN, pf, b1 + l * FFN, nullptr, NTOK, FFN, CC);
        // FFN2: x += f @ W2 + b2
        sgemm_kernel<2><<<dim3(CC / GBN, NTOK / GBM), 256>>>(
            pf, W2 + (size_t)l * FFN * CC, px, b2 + l * CC, px, NTOK, CC, FFN);
    }

    ln_kernel<<<NTOK, CC>>>(px, ph, lnfg, lnfb);
    cls_kernel<<<BB, CLS_H * 2>>>(Wc1, bc1, Wc2, bc2, out);
}

// round 4
// speedup vs baseline: 14.3781x; 2.6579x over previous
#include <cuda_runtime.h>
#include <cuda_bf16.h>
#include <math.h>

// Problem constants
#define BB 4
#define TT 2048
#define CC 256
#define HH 8
#define HS 32
#define LL 4
#define FFN 256
#define CLS_H 512
#define N_OUT 10
#define NTOK (BB*TT)          // 8192

// ---------------- scratch (device globals; no allocations allowed) ----------
__device__ float g_x   [NTOK*CC];                 // residual stream
__device__ float g_h   [NTOK*CC];                 // LN output / scratch
__device__ float g_o   [NTOK*CC];                 // attention output (heads concat)
__device__ float g_f   [NTOK*FFN];                // FFN hidden
__device__ float g_wqkv[CC*3*CC];                 // repacked QKV weight [K=256, N=768]
__device__ __nv_bfloat16 g_qkvb[NTOK*3*CC];       // bf16 qkv (q pre-scaled by 1/16)
__device__ __nv_bfloat16 g_vt  [BB*HH*HS*TT];     // V transposed: [bh][d][t]

// ---------------- embedding ------------------------------------------------
__global__ void embed_kernel(const int* __restrict__ idx,
                             const float* __restrict__ tok,
                             const float* __restrict__ pos) {
    int i = blockIdx.x;
    int c = threadIdx.x;
    int t = i & (TT - 1);
    g_x[(size_t)i * CC + c] = tok[(size_t)idx[i] * CC + c] + pos[(size_t)t * CC + c];
}

// ---------------- LayerNorm ------------------------------------------------
__global__ void ln_kernel(const float* __restrict__ x, float* __restrict__ y,
                          const float* __restrict__ g, const float* __restrict__ b) {
    int row = blockIdx.x;
    int c   = threadIdx.x;
    __shared__ float red1[8];
    __shared__ float red2[8];

    float v = x[(size_t)row * CC + c];

    float s = v;
    #pragma unroll
    for (int o = 16; o > 0; o >>= 1) s += __shfl_xor_sync(0xffffffffu, s, o);
    if ((c & 31) == 0) red1[c >> 5] = s;
    __syncthreads();
    float tot = 0.f;
    #pragma unroll
    for (int i = 0; i < 8; i++) tot += red1[i];
    float mean = tot * (1.0f / CC);

    float d  = v - mean;
    float s2 = d * d;
    #pragma unroll
    for (int o = 16; o > 0; o >>= 1) s2 += __shfl_xor_sync(0xffffffffu, s2, o);
    if ((c & 31) == 0) red2[c >> 5] = s2;
    __syncthreads();
    float tot2 = 0.f;
    #pragma unroll
    for (int i = 0; i < 8; i++) tot2 += red2[i];
    float var = tot2 * (1.0f / CC);

    y[(size_t)row * CC + c] = d * rsqrtf(var + 1e-5f) * g[c] + b[c];
}

// ---------------- repack Wq/Wk/Wv[layer] -> [256, 768] row-major ------------
__global__ void repack_qkv_kernel(const float* __restrict__ Wq,
                                  const float* __restrict__ Wk,
                                  const float* __restrict__ Wv, int layer) {
    int i = blockIdx.x * 256 + threadIdx.x;
    int d = i & 31;
    int c = (i >> 5) & 255;
    int h = (i >> 13) & 7;
    int s = i >> 16;
    const float* W = (s == 0) ? Wq : (s == 1) ? Wk : Wv;
    float val = W[(size_t)layer * HH * CC * HS + (size_t)h * CC * HS + (size_t)c * HS + d];
    g_wqkv[(size_t)c * (3 * CC) + s * CC + h * HS + d] = val;
}

// ---------------- fp32 tiled SGEMM (proj / ffn) -----------------------------
// EPI: 2 = bias + residual, 3 = bias + relu
#define GBM 128
#define GBN 64
#define GBK 16
template <int EPI>
__global__ void __launch_bounds__(256)
sgemm_kernel(const float* __restrict__ A, const float* __restrict__ B,
             float* __restrict__ C, const float* __restrict__ bias,
             const float* __restrict__ res, int M, int N, int K) {
    __shared__ float As[GBK][GBM];
    __shared__ float Bs[GBK][GBN];
    int m0 = blockIdx.y * GBM;
    int n0 = blockIdx.x * GBN;
    int tid = threadIdx.x;
    int tx = tid & 15;
    int ty = tid >> 4;

    float acc[8][4];
    #pragma unroll
    for (int i = 0; i < 8; i++)
        #pragma unroll
        for (int j = 0; j < 4; j++) acc[i][j] = 0.f;

    int aRow0 = tid >> 2;
    int aC0   = (tid & 3) * 4;
    int aRow1 = (tid + 256) >> 2;
    int bK  = tid >> 4;
    int bC  = (tid & 15) * 4;

    for (int k0 = 0; k0 < K; k0 += GBK) {
        float4 a0 = *(const float4*)(A + (size_t)(m0 + aRow0) * K + k0 + aC0);
        float4 a1 = *(const float4*)(A + (size_t)(m0 + aRow1) * K + k0 + aC0);
        float4 bv = *(const float4*)(B + (size_t)(k0 + bK) * N + n0 + bC);
        As[aC0 + 0][aRow0] = a0.x;
        As[aC0 + 1][aRow0] = a0.y;
        As[aC0 + 2][aRow0] = a0.z;
        As[aC0 + 3][aRow0] = a0.w;
        As[aC0 + 0][aRow1] = a1.x;
        As[aC0 + 1][aRow1] = a1.y;
        As[aC0 + 2][aRow1] = a1.z;
        As[aC0 + 3][aRow1] = a1.w;
        *(float4*)&Bs[bK][bC] = bv;
        __syncthreads();
        #pragma unroll
        for (int k = 0; k < GBK; k++) {
            float4 ra0 = *(const float4*)&As[k][ty * 8];
            float4 ra1 = *(const float4*)&As[k][ty * 8 + 4];
            float4 rb  = *(const float4*)&Bs[k][tx * 4];
            float ra[8] = {ra0.x, ra0.y, ra0.z, ra0.w, ra1.x, ra1.y, ra1.z, ra1.w};
            float rbv[4] = {rb.x, rb.y, rb.z, rb.w};
            #pragma unroll
            for (int i = 0; i < 8; i++)
                #pragma unroll
                for (int j = 0; j < 4; j++) acc[i][j] += ra[i] * rbv[j];
        }
        __syncthreads();
    }

    #pragma unroll
    for (int i = 0; i < 8; i++) {
        int m = m0 + ty * 8 + i;
        #pragma unroll
        for (int j = 0; j < 4; j++) {
            int n = n0 + tx * 4 + j;
            float v = acc[i][j];
            if (EPI >= 2) v += bias[n];
            if (EPI == 2) v += res[(size_t)m * N + n];
            if (EPI == 3) v = fmaxf(v, 0.f);
            C[(size_t)m * N + n] = v;
        }
    }
}

// ---------------- QKV SGEMM, bf16 output, q pre-scaled by 1/16 --------------
__global__ void __launch_bounds__(256)
sgemm_qkv_kernel(const float* __restrict__ A, const float* __restrict__ B,
                 __nv_bfloat16* __restrict__ C, int M, int N, int K) {
    __shared__ float As[GBK][GBM];
    __shared__ float Bs[GBK][GBN];
    int m0 = blockIdx.y * GBM;
    int n0 = blockIdx.x * GBN;
    int tid = threadIdx.x;
    int tx = tid & 15;
    int ty = tid >> 4;

    float acc[8][4];
    #pragma unroll
    for (int i = 0; i < 8; i++)
        #pragma unroll
        for (int j = 0; j < 4; j++) acc[i][j] = 0.f;

    int aRow0 = tid >> 2;
    int aC0   = (tid & 3) * 4;
    int aRow1 = (tid + 256) >> 2;
    int bK  = tid >> 4;
    int bC  = (tid & 15) * 4;

    for (int k0 = 0; k0 < K; k0 += GBK) {
        float4 a0 = *(const float4*)(A + (size_t)(m0 + aRow0) * K + k0 + aC0);
        float4 a1 = *(const float4*)(A + (size_t)(m0 + aRow1) * K + k0 + aC0);
        float4 bv = *(const float4*)(B + (size_t)(k0 + bK) * N + n0 + bC);
        As[aC0 + 0][aRow0] = a0.x;
        As[aC0 + 1][aRow0] = a0.y;
        As[aC0 + 2][aRow0] = a0.z;
        As[aC0 + 3][aRow0] = a0.w;
        As[aC0 + 0][aRow1] = a1.x;
        As[aC0 + 1][aRow1] = a1.y;
        As[aC0 + 2][aRow1] = a1.z;
        As[aC0 + 3][aRow1] = a1.w;
        *(float4*)&Bs[bK][bC] = bv;
        __syncthreads();
        #pragma unroll
        for (int k = 0; k < GBK; k++) {
            float4 ra0 = *(const float4*)&As[k][ty * 8];
            float4 ra1 = *(const float4*)&As[k][ty * 8 + 4];
            float4 rb  = *(const float4*)&Bs[k][tx * 4];
            float ra[8] = {ra0.x, ra0.y, ra0.z, ra0.w, ra1.x, ra1.y, ra1.z, ra1.w};
            float rbv[4] = {rb.x, rb.y, rb.z, rb.w};
            #pragma unroll
            for (int i = 0; i < 8; i++)
                #pragma unroll
                for (int j = 0; j < 4; j++) acc[i][j] += ra[i] * rbv[j];
        }
        __syncthreads();
    }

    float qs = (n0 < CC) ? 0.0625f : 1.0f;   // whole 64-col tile is q or not
    #pragma unroll
    for (int i = 0; i < 8; i++) {
        int m = m0 + ty * 8 + i;
        #pragma unroll
        for (int j2 = 0; j2 < 2; j2++) {
            int n = n0 + tx * 4 + j2 * 2;
            __nv_bfloat162 p;
            p.x = __float2bfloat16(acc[i][j2 * 2 + 0] * qs);
            p.y = __float2bfloat16(acc[i][j2 * 2 + 1] * qs);
            *(__nv_bfloat162*)(C + (size_t)m * N + n) = p;
        }
    }
}

// ---------------- V transpose: g_vt[bh][d][t] = v(bf16) ---------------------
__global__ void vtrans_kernel(void) {
    int bh = blockIdx.y;
    int b = bh >> 3, h = bh & 7;
    int j0 = blockIdx.x * 64;
    __shared__ __nv_bfloat16 tile[64][33];
    int tid = threadIdx.x;
    #pragma unroll
    for (int i = tid; i < 2048; i += 256) {
        int j = i >> 5, d = i & 31;
        tile[j][d] = g_qkvb[(size_t)(b * TT + j0 + j) * 768 + 512 + h * HS + d];
    }
    __syncthreads();
    #pragma unroll
    for (int i = tid; i < 2048; i += 256) {
        int d = i >> 6, j = i & 63;
        g_vt[((size_t)bh * HS + d) * TT + j0 + j] = tile[j][d];
    }
}

// ---------------- bf16 mma helper -------------------------------------------
__device__ __forceinline__ void mma16816(float c[4],
        unsigned a0, unsigned a1, unsigned a2, unsigned a3,
        unsigned b0, unsigned b1) {
    asm volatile(
        "mma.sync.aligned.m16n8k16.row.col.f32.bf16.bf16.f32 "
        "{%0,%1,%2,%3}, {%4,%5,%6,%7}, {%8,%9}, {%0,%1,%2,%3};"
        : "+f"(c[0]), "+f"(c[1]), "+f"(c[2]), "+f"(c[3])
        : "r"(a0), "r"(a1), "r"(a2), "r"(a3), "r"(b0), "r"(b1));
}

// ---------------- flash attention with bf16 HMMA ----------------------------
// grid (T/64, B*H), block 128 (4 warps). Warp w owns q rows [w*16, w*16+16).
// Q pre-scaled by 1/16 in the QKV GEMM.
__global__ void __launch_bounds__(128) attn_kernel(void) {
    int bh = blockIdx.y;
    int b = bh >> 3, h = bh & 7;
    int t0 = blockIdx.x * 64;

    __shared__ __nv_bfloat16 Ks[64][40];   // keys row-major [j][d], pad->20 words
    __shared__ __nv_bfloat16 Vt[32][72];   // V transposed [d][j], pad->36 words

    int tid = threadIdx.x;
    int w = tid >> 5, lane = tid & 31;
    int gr = lane >> 2, ci = lane & 3;

    // Q fragments from global (bf16, already scaled)
    unsigned qa[2][4];
    {
        const __nv_bfloat16* qbase = g_qkvb + (size_t)(b * TT + t0 + w * 16) * 768 + h * HS;
        #pragma unroll
        for (int ks = 0; ks < 2; ks++) {
            qa[ks][0] = *(const unsigned*)(qbase + (size_t)(gr)     * 768 + 16 * ks + 2 * ci);
            qa[ks][1] = *(const unsigned*)(qbase + (size_t)(gr + 8) * 768 + 16 * ks + 2 * ci);
            qa[ks][2] = *(const unsigned*)(qbase + (size_t)(gr)     * 768 + 16 * ks + 2 * ci + 8);
            qa[ks][3] = *(const unsigned*)(qbase + (size_t)(gr + 8) * 768 + 16 * ks + 2 * ci + 8);
        }
    }

    float Of[4][4];
    #pragma unroll
    for (int i = 0; i < 4; i++)
        #pragma unroll
        for (int j = 0; j < 4; j++) Of[i][j] = 0.f;
    float m0 = -1e30f, m1 = -1e30f, l0 = 0.f, l1 = 0.f;

    for (int j0 = 0; j0 < TT; j0 += 64) {
        __syncthreads();
        // K tile: 64 rows x 32 bf16 = 256 x 16B
        #pragma unroll
        for (int i = tid; i < 256; i += 128) {
            int r = i >> 2, w4 = i & 3;
            *(float4*)&Ks[r][w4 * 8] =
                *(const float4*)(g_qkvb + (size_t)(b * TT + j0 + r) * 768 + CC + h * HS + w4 * 8);
        }
        // Vt tile: 32 rows x 64 bf16 = 256 x 16B
        #pragma unroll
        for (int i = tid; i < 256; i += 128) {
            int d = i >> 3, c8 = i & 7;
            *(float4*)&Vt[d][c8 * 8] =
                *(const float4*)(g_vt + ((size_t)bh * HS + d) * TT + j0 + c8 * 8);
        }
        __syncthreads();

        // S = Q @ K^T  (M16 per warp, N64, K32)
        float S[8][4];
        #pragma unroll
        for (int nt = 0; nt < 8; nt++)
            #pragma unroll
            for (int j = 0; j < 4; j++) S[nt][j] = 0.f;
        const unsigned* Ks32 = (const unsigned*)Ks;
        #pragma unroll
        for (int nt = 0; nt < 8; nt++) {
            int row = nt * 8 + gr;
            #pragma unroll
            for (int ks = 0; ks < 2; ks++) {
                unsigned b0 = Ks32[row * 20 + ks * 8 + ci];
                unsigned b1 = Ks32[row * 20 + ks * 8 + ci + 4];
                mma16816(S[nt], qa[ks][0], qa[ks][1], qa[ks][2], qa[ks][3], b0, b1);
            }
        }

        // online softmax in fragments
        float cm0 = -1e30f, cm1 = -1e30f;
        #pragma unroll
        for (int nt = 0; nt < 8; nt++) {
            cm0 = fmaxf(cm0, fmaxf(S[nt][0], S[nt][1]));
            cm1 = fmaxf(cm1, fmaxf(S[nt][2], S[nt][3]));
        }
        cm0 = fmaxf(cm0, __shfl_xor_sync(0xffffffffu, cm0, 1));
        cm0 = fmaxf(cm0, __shfl_xor_sync(0xffffffffu, cm0, 2));
        cm1 = fmaxf(cm1, __shfl_xor_sync(0xffffffffu, cm1, 1));
        cm1 = fmaxf(cm1, __shfl_xor_sync(0xffffffffu, cm1, 2));
        float mn0 = fmaxf(m0, cm0);
        float mn1 = fmaxf(m1, cm1);
        float a0 = __expf(m0 - mn0);
        float a1 = __expf(m1 - mn1);
        m0 = mn0; m1 = mn1;
        l0 *= a0; l1 *= a1;
        #pragma unroll
        for (int nt = 0; nt < 4; nt++) {
            Of[nt][0] *= a0; Of[nt][1] *= a0;
            Of[nt][2] *= a1; Of[nt][3] *= a1;
        }

        unsigned pa[4][4];
        #pragma unroll
        for (int nt = 0; nt < 8; nt++) {
            float p0 = __expf(S[nt][0] - mn0);
            float p1 = __expf(S[nt][1] - mn0);
            float p2 = __expf(S[nt][2] - mn1);
            float p3 = __expf(S[nt][3] - mn1);
            l0 += p0 + p1;
            l1 += p2 + p3;
            __nv_bfloat162 lo = __float22bfloat162_rn(make_float2(p0, p1));
            __nv_bfloat162 hi = __float22bfloat162_rn(make_float2(p2, p3));
            int kk = nt >> 1, half = nt & 1;
            pa[kk][half * 2 + 0] = *(unsigned*)&lo;
            pa[kk][half * 2 + 1] = *(unsigned*)&hi;
        }

        // O += P @ V  (M16, N32, K64)
        const unsigned* Vt32 = (const unsigned*)Vt;
        #pragma unroll
        for (int kk = 0; kk < 4; kk++) {
            #pragma unroll
            for (int nt = 0; nt < 4; nt++) {
                int drow = nt * 8 + gr;
                unsigned b0 = Vt32[drow * 36 + kk * 8 + ci];
                unsigned b1 = Vt32[drow * 36 + kk * 8 + ci + 4];
                mma16816(Of[nt], pa[kk][0], pa[kk][1], pa[kk][2], pa[kk][3], b0, b1);
            }
        }
    }

    l0 += __shfl_xor_sync(0xffffffffu, l0, 1);
    l0 += __shfl_xor_sync(0xffffffffu, l0, 2);
    l1 += __shfl_xor_sync(0xffffffffu, l1, 1);
    l1 += __shfl_xor_sync(0xffffffffu, l1, 2);
    float i0 = 1.0f / l0;
    float i1 = 1.0f / l1;

    float* ob = g_o + (size_t)(b * TT + t0 + w * 16) * CC + h * HS;
    #pragma unroll
    for (int nt = 0; nt < 4; nt++) {
        float2 lo = make_float2(Of[nt][0] * i0, Of[nt][1] * i0);
        float2 hi = make_float2(Of[nt][2] * i1, Of[nt][3] * i1);
        *(float2*)(ob + (size_t)(gr)     * CC + nt * 8 + 2 * ci) = lo;
        *(float2*)(ob + (size_t)(gr + 8) * CC + nt * 8 + 2 * ci) = hi;
    }
}

// ---------------- classifier ------------------------------------------------
__global__ void __launch_bounds__(1024) cls_kernel(
        const float* __restrict__ Wc1, const float* __restrict__ bc1,
        const float* __restrict__ Wc2, const float* __restrict__ bc2,
        float* __restrict__ out) {
    int b = blockIdx.x;
    int tid = threadIdx.x;
    __shared__ float emb4[4][CC];
    __shared__ float emb[CC];
    __shared__ float hid[CLS_H];
    __shared__ float lg[N_OUT];

    {
        int c   = tid & 255;
        int qtr = tid >> 8;
        float sum = 0.f;
        const float* base = g_h + (size_t)b * TT * CC + (size_t)qtr * 512 * CC + c;
        for (int t = 0; t < 512; t++) sum += base[(size_t)t * CC];
        emb4[qtr][c] = sum;
    }
    __syncthreads();
    if (tid < CC) {
        emb[tid] = (emb4[0][tid] + emb4[1][tid] + emb4[2][tid] + emb4[3][tid]) * (1.0f / TT);
    }
    __syncthreads();

    if (tid < CLS_H) {
        float sum = bc1[tid];
        for (int c = 0; c < CC; c++) sum += emb[c] * Wc1[(size_t)c * CLS_H + tid];
        hid[tid] = fmaxf(sum, 0.f);
    }
    __syncthreads();

    if (tid < N_OUT) {
        float sum = bc2[tid];
        for (int k = 0; k < CLS_H; k++) sum += hid[k] * Wc2[(size_t)k * N_OUT + tid];
        lg[tid] = sum;
    }
    __syncthreads();

    if (tid == 0) {
        float mx = lg[0];
        for (int j = 1; j < N_OUT; j++) mx = fmaxf(mx, lg[j]);
        float e[N_OUT], se = 0.f;
        for (int j = 0; j < N_OUT; j++) { e[j] = __expf(lg[j] - mx); se += e[j]; }
        float inv = 1.0f / se;
        for (int j = 0; j < N_OUT; j++) out[b * N_OUT + j] = e[j] * inv;
    }
}

// ---------------- launch ----------------------------------------------------
extern "C" void kernel_launch(void* const* d_in, const int* in_sizes, int n_in,
                              void* d_out, int out_size) {
    const int*   idx   = (const int*)  d_in[0];
    const float* tok   = (const float*)d_in[1];
    const float* pos   = (const float*)d_in[2];
    const float* Wq    = (const float*)d_in[3];
    const float* Wk    = (const float*)d_in[4];
    const float* Wv    = (const float*)d_in[5];
    const float* Wproj = (const float*)d_in[6];
    const float* bproj = (const float*)d_in[7];
    const float* ln1g  = (const float*)d_in[8];
    const float* ln1b  = (const float*)d_in[9];
    const float* ln2g  = (const float*)d_in[10];
    const float* ln2b  = (const float*)d_in[11];
    const float* W1    = (const float*)d_in[12];
    const float* b1    = (const float*)d_in[13];
    const float* W2    = (const float*)d_in[14];
    const float* b2    = (const float*)d_in[15];
    const float* lnfg  = (const float*)d_in[16];
    const float* lnfb  = (const float*)d_in[17];
    const float* Wc1   = (const float*)d_in[18];
    const float* bc1   = (const float*)d_in[19];
    const float* Wc2   = (const float*)d_in[20];
    const float* bc2   = (const float*)d_in[21];
    float* out = (float*)d_out;

    float *px, *ph, *po, *pf, *pwqkv;
    __nv_bfloat16* pqkvb;
    cudaGetSymbolAddress((void**)&px,    g_x);
    cudaGetSymbolAddress((void**)&ph,    g_h);
    cudaGetSymbolAddress((void**)&po,    g_o);
    cudaGetSymbolAddress((void**)&pf,    g_f);
    cudaGetSymbolAddress((void**)&pwqkv, g_wqkv);
    cudaGetSymbolAddress((void**)&pqkvb, g_qkvb);

    embed_kernel<<<NTOK, CC>>>(idx, tok, pos);

    for (int l = 0; l < LL; l++) {
        ln_kernel<<<NTOK, CC>>>(px, ph, ln1g + l * CC, ln1b + l * CC);
        repack_qkv_kernel<<<(3 * HH * CC * HS) / 256, 256>>>(Wq, Wk, Wv, l);
        // QKV: [8192,256]@[256,768] -> bf16 (q scaled by 1/16)
        sgemm_qkv_kernel<<<dim3((3 * CC) / GBN, NTOK / GBM), 256>>>(
            ph, pwqkv, pqkvb, NTOK, 3 * CC, CC);
        vtrans_kernel<<<dim3(TT / 64, BB * HH), 256>>>();
        attn_kernel<<<dim3(TT / 64, BB * HH), 128>>>();
        // proj + bias + residual -> x
        sgemm_kernel<2><<<dim3(CC / GBN, NTOK / GBM), 256>>>(
            po, Wproj + (size_t)l * CC * CC, px, bproj + l * CC, px, NTOK, CC, CC);
        ln_kernel<<<NTOK, CC>>>(px, ph, ln2g + l * CC, ln2b + l * CC);
        // FFN1: relu(h @ W1 + b1)
        sgemm_kernel<3><<<dim3(FFN / GBN, NTOK / GBM), 256>>>(
            ph, W1 + (size_t)l * CC * FFN, pf, b1 + l * FFN, nullptr, NTOK, FFN, CC);
        // FFN2: x += f @ W2 + b2
        sgemm_kernel<2><<<dim3(CC / GBN, NTOK / GBM), 256>>>(
            pf, W2 + (size_t)l * FFN * CC, px, b2 + l * CC, px, NTOK, CC, FFN);
    }

    ln_kernel<<<NTOK, CC>>>(px, ph, lnfg, lnfb);
    cls_kernel<<<BB, CLS_H * 2>>>(Wc1, bc1, Wc2, bc2, out);
}

// round 5
// speedup vs baseline: 28.0737x; 1.9525x over previous
#include <cuda_runtime.h>
#include <cuda_bf16.h>
#include <math.h>

// Problem constants
#define BB 4
#define TT 2048
#define CC 256
#define HH 8
#define HS 32
#define LL 4
#define FFN 256
#define CLS_H 512
#define N_OUT 10
#define NTOK (BB*TT)          // 8192

// ---------------- scratch (device globals; no allocations allowed) ----------
__device__ float g_x[NTOK*CC];                       // fp32 residual stream
__device__ __nv_bfloat16 g_hb  [NTOK*CC];            // bf16 LN output
__device__ __nv_bfloat16 g_qkvb[NTOK*3*CC];          // bf16 qkv (q pre-scaled 1/16)
__device__ __nv_bfloat16 g_ob  [NTOK*CC];            // bf16 attention output
__device__ __nv_bfloat16 g_fb  [NTOK*FFN];           // bf16 FFN hidden
__device__ __nv_bfloat16 g_vt  [BB*HH*HS*TT];        // V transposed [bh][d][t]
__device__ __nv_bfloat16 g_wqkvb [LL*768*CC];        // [l][n][k] n=s*256+h*32+d
__device__ __nv_bfloat16 g_wprojb[LL*CC*CC];         // [l][n][k] = Wproj[l][k][n]
__device__ __nv_bfloat16 g_w1b   [LL*CC*FFN];        // [l][n][k] = W1[l][k][n]
__device__ __nv_bfloat16 g_w2b   [LL*FFN*CC];        // [l][n][k] = W2[l][k][n]

// ---------------- embedding ------------------------------------------------
__global__ void embed_kernel(const int* __restrict__ idx,
                             const float* __restrict__ tok,
                             const float* __restrict__ pos) {
    int i = blockIdx.x;
    int c = threadIdx.x;
    int t = i & (TT - 1);
    g_x[(size_t)i * CC + c] = tok[(size_t)idx[i] * CC + c] + pos[(size_t)t * CC + c];
}

// ---------------- weight convert+transpose to bf16 (once per launch) --------
#define WQKV_SZ (LL*768*CC)
#define WSQ_SZ  (LL*CC*CC)
__global__ void wconv_kernel(const float* __restrict__ Wq, const float* __restrict__ Wk,
                             const float* __restrict__ Wv, const float* __restrict__ Wproj,
                             const float* __restrict__ W1, const float* __restrict__ W2) {
    int idx = blockIdx.x * 256 + threadIdx.x;
    if (idx < WQKV_SZ) {
        int k = idx & 255;
        int n = (idx >> 8) % 768;
        int l = idx / (768 * CC);
        int s = n >> 8, h = (n >> 5) & 7, d = n & 31;
        const float* W = (s == 0) ? Wq : (s == 1) ? Wk : Wv;
        g_wqkvb[idx] = __float2bfloat16(W[(((size_t)l * HH + h) * CC + k) * HS + d]);
    } else {
        int j = idx - WQKV_SZ;
        int seg = j / WSQ_SZ;            // 0=proj 1=w1 2=w2
        int r = j % WSQ_SZ;
        int k = r & 255, n = (r >> 8) & 255, l = r >> 16;
        const float* W = (seg == 0) ? Wproj : (seg == 1) ? W1 : W2;
        float v = W[((size_t)l * CC + k) * CC + n];
        __nv_bfloat16* D = (seg == 0) ? g_wprojb : (seg == 1) ? g_w1b : g_w2b;
        D[r] = __float2bfloat16(v);
    }
}

// ---------------- LayerNorm: warp per token, bf16 out ------------------------
__global__ void __launch_bounds__(256) ln_bf16_kernel(
        const float* __restrict__ x, __nv_bfloat16* __restrict__ y,
        const float* __restrict__ g, const float* __restrict__ b) {
    int tokn = blockIdx.x * 8 + (threadIdx.x >> 5);
    int lane = threadIdx.x & 31;
    const float* xp = x + (size_t)tokn * CC + lane * 8;
    float4 v0 = *(const float4*)(xp);
    float4 v1 = *(const float4*)(xp + 4);
    float vv[8] = {v0.x, v0.y, v0.z, v0.w, v1.x, v1.y, v1.z, v1.w};

    float s = 0.f, s2 = 0.f;
    #pragma unroll
    for (int i = 0; i < 8; i++) { s += vv[i]; s2 += vv[i] * vv[i]; }
    #pragma unroll
    for (int o = 16; o > 0; o >>= 1) {
        s  += __shfl_xor_sync(0xffffffffu, s, o);
        s2 += __shfl_xor_sync(0xffffffffu, s2, o);
    }
    float mean = s * (1.0f / CC);
    float var  = s2 * (1.0f / CC) - mean * mean;
    float rstd = rsqrtf(var + 1e-5f);

    float4 g0 = *(const float4*)(g + lane * 8);
    float4 g1 = *(const float4*)(g + lane * 8 + 4);
    float4 b0 = *(const float4*)(b + lane * 8);
    float4 b1 = *(const float4*)(b + lane * 8 + 4);
    float gg[8] = {g0.x, g0.y, g0.z, g0.w, g1.x, g1.y, g1.z, g1.w};
    float bb[8] = {b0.x, b0.y, b0.z, b0.w, b1.x, b1.y, b1.z, b1.w};

    unsigned outp[4];
    #pragma unroll
    for (int p = 0; p < 4; p++) {
        __nv_bfloat162 h2 = __float22bfloat162_rn(make_float2(
            (vv[2*p+0] - mean) * rstd * gg[2*p+0] + bb[2*p+0],
            (vv[2*p+1] - mean) * rstd * gg[2*p+1] + bb[2*p+1]));
        outp[p] = *(unsigned*)&h2;
    }
    *(uint4*)(y + (size_t)tokn * CC + lane * 8) = make_uint4(outp[0], outp[1], outp[2], outp[3]);
}

// ---------------- bf16 mma helper -------------------------------------------
__device__ __forceinline__ void mma16816(float c[4],
        unsigned a0, unsigned a1, unsigned a2, unsigned a3,
        unsigned b0, unsigned b1) {
    asm volatile(
        "mma.sync.aligned.m16n8k16.row.col.f32.bf16.bf16.f32 "
        "{%0,%1,%2,%3}, {%4,%5,%6,%7}, {%8,%9}, {%0,%1,%2,%3};"
        : "+f"(c[0]), "+f"(c[1]), "+f"(c[2]), "+f"(c[3])
        : "r"(a0), "r"(a1), "r"(a2), "r"(a3), "r"(b0), "r"(b1));
}

// ---------------- bf16 HMMA GEMM: C[M,N] = A[M,K] @ Bt[N,K]^T + epilogue ----
// A row-major bf16, Bt row-major bf16 (pre-transposed weight). K multiple of 64.
// EPI 0: bf16 store, cols<256 scaled by 1/16 (qkv)
// EPI 2: fp32 bias + residual in-place
// EPI 3: bf16 bias + relu
#define HGM 128
#define HGN 64
#define HGK 64
#define HPAD 8
template <int EPI>
__global__ void __launch_bounds__(256) hgemm_kernel(
        const __nv_bfloat16* __restrict__ A, const __nv_bfloat16* __restrict__ Bt,
        void* __restrict__ Cout, const float* __restrict__ bias,
        float* __restrict__ res, int M, int N, int K) {
    __shared__ __nv_bfloat16 As[HGM][HGK + HPAD];   // stride 72 bf16 = 36 words
    __shared__ __nv_bfloat16 Bs[HGN][HGK + HPAD];

    int m0 = blockIdx.y * HGM;
    int n0 = blockIdx.x * HGN;
    int tid = threadIdx.x;
    int w = tid >> 5, lane = tid & 31;
    int wm = w >> 1, wn = w & 1;         // 4 x 2 warp grid
    int gr = lane >> 2, ci = lane & 3;

    float acc[2][4][4];
    #pragma unroll
    for (int mt = 0; mt < 2; mt++)
        #pragma unroll
        for (int nt = 0; nt < 4; nt++)
            #pragma unroll
            for (int r = 0; r < 4; r++) acc[mt][nt][r] = 0.f;

    const unsigned* As32 = (const unsigned*)As;
    const unsigned* Bs32 = (const unsigned*)Bs;

    for (int k0 = 0; k0 < K; k0 += HGK) {
        __syncthreads();
        // A tile: 128 rows x 64 bf16 = 1024 float4, 4 per thread
        #pragma unroll
        for (int i = 0; i < 4; i++) {
            int idx = tid + i * 256;
            int row = idx >> 3, j = idx & 7;
            *(float4*)&As[row][j * 8] =
                *(const float4*)(A + (size_t)(m0 + row) * K + k0 + j * 8);
        }
        // B tile: 64 rows x 64 bf16 = 512 float4, 2 per thread
        #pragma unroll
        for (int i = 0; i < 2; i++) {
            int idx = tid + i * 256;
            int row = idx >> 3, j = idx & 7;
            *(float4*)&Bs[row][j * 8] =
                *(const float4*)(Bt + (size_t)(n0 + row) * K + k0 + j * 8);
        }
        __syncthreads();

        #pragma unroll
        for (int ks = 0; ks < 4; ks++) {
            unsigned a[2][4];
            #pragma unroll
            for (int mt = 0; mt < 2; mt++) {
                int r = wm * 32 + mt * 16 + gr;
                a[mt][0] = As32[(size_t)r       * 36 + ks * 8 + ci];
                a[mt][1] = As32[(size_t)(r + 8) * 36 + ks * 8 + ci];
                a[mt][2] = As32[(size_t)r       * 36 + ks * 8 + ci + 4];
                a[mt][3] = As32[(size_t)(r + 8) * 36 + ks * 8 + ci + 4];
            }
            unsigned bf[4][2];
            #pragma unroll
            for (int nt = 0; nt < 4; nt++) {
                int nr = wn * 32 + nt * 8 + gr;
                bf[nt][0] = Bs32[(size_t)nr * 36 + ks * 8 + ci];
                bf[nt][1] = Bs32[(size_t)nr * 36 + ks * 8 + ci + 4];
            }
            #pragma unroll
            for (int mt = 0; mt < 2; mt++)
                #pragma unroll
                for (int nt = 0; nt < 4; nt++)
                    mma16816(acc[mt][nt], a[mt][0], a[mt][1], a[mt][2], a[mt][3],
                             bf[nt][0], bf[nt][1]);
        }
    }

    // epilogue
    #pragma unroll
    for (int mt = 0; mt < 2; mt++) {
        int row0 = m0 + wm * 32 + mt * 16 + gr;
        int row1 = row0 + 8;
        #pragma unroll
        for (int nt = 0; nt < 4; nt++) {
            int col = n0 + wn * 32 + nt * 8 + 2 * ci;
            float c0 = acc[mt][nt][0], c1 = acc[mt][nt][1];
            float c2 = acc[mt][nt][2], c3 = acc[mt][nt][3];
            if (EPI == 0) {
                float qs = (n0 < 256) ? 0.0625f : 1.0f;
                __nv_bfloat16* C = (__nv_bfloat16*)Cout;
                __nv_bfloat162 lo = __float22bfloat162_rn(make_float2(c0 * qs, c1 * qs));
                __nv_bfloat162 hi = __float22bfloat162_rn(make_float2(c2 * qs, c3 * qs));
                *(__nv_bfloat162*)(C + (size_t)row0 * N + col) = lo;
                *(__nv_bfloat162*)(C + (size_t)row1 * N + col) = hi;
            } else if (EPI == 2) {
                float* C = (float*)Cout;
                float bz0 = bias[col], bz1 = bias[col + 1];
                float2 r0 = *(float2*)(res + (size_t)row0 * N + col);
                float2 r1 = *(float2*)(res + (size_t)row1 * N + col);
                *(float2*)(C + (size_t)row0 * N + col) = make_float2(c0 + bz0 + r0.x, c1 + bz1 + r0.y);
                *(float2*)(C + (size_t)row1 * N + col) = make_float2(c2 + bz0 + r1.x, c3 + bz1 + r1.y);
            } else {
                __nv_bfloat16* C = (__nv_bfloat16*)Cout;
                float bz0 = bias[col], bz1 = bias[col + 1];
                __nv_bfloat162 lo = __float22bfloat162_rn(make_float2(fmaxf(c0 + bz0, 0.f), fmaxf(c1 + bz1, 0.f)));
                __nv_bfloat162 hi = __float22bfloat162_rn(make_float2(fmaxf(c2 + bz0, 0.f), fmaxf(c3 + bz1, 0.f)));
                *(__nv_bfloat162*)(C + (size_t)row0 * N + col) = lo;
                *(__nv_bfloat162*)(C + (size_t)row1 * N + col) = hi;
            }
        }
    }
}

// ---------------- V transpose: g_vt[bh][d][t] --------------------------------
__global__ void vtrans_kernel(void) {
    int bh = blockIdx.y;
    int b = bh >> 3, h = bh & 7;
    int j0 = blockIdx.x * 64;
    __shared__ __nv_bfloat16 tile[64][33];
    int tid = threadIdx.x;
    #pragma unroll
    for (int i = tid; i < 2048; i += 256) {
        int j = i >> 5, d = i & 31;
        tile[j][d] = g_qkvb[(size_t)(b * TT + j0 + j) * 768 + 512 + h * HS + d];
    }
    __syncthreads();
    #pragma unroll
    for (int i = tid; i < 2048; i += 256) {
        int d = i >> 6, j = i & 63;
        g_vt[((size_t)bh * HS + d) * TT + j0 + j] = tile[j][d];
    }
}

// ---------------- flash attention with bf16 HMMA ----------------------------
__global__ void __launch_bounds__(128) attn_kernel(void) {
    int bh = blockIdx.y;
    int b = bh >> 3, h = bh & 7;
    int t0 = blockIdx.x * 64;

    __shared__ __nv_bfloat16 Ks[64][40];
    __shared__ __nv_bfloat16 Vt[32][72];

    int tid = threadIdx.x;
    int w = tid >> 5, lane = tid & 31;
    int gr = lane >> 2, ci = lane & 3;

    unsigned qa[2][4];
    {
        const __nv_bfloat16* qbase = g_qkvb + (size_t)(b * TT + t0 + w * 16) * 768 + h * HS;
        #pragma unroll
        for (int ks = 0; ks < 2; ks++) {
            qa[ks][0] = *(const unsigned*)(qbase + (size_t)(gr)     * 768 + 16 * ks + 2 * ci);
            qa[ks][1] = *(const unsigned*)(qbase + (size_t)(gr + 8) * 768 + 16 * ks + 2 * ci);
            qa[ks][2] = *(const unsigned*)(qbase + (size_t)(gr)     * 768 + 16 * ks + 2 * ci + 8);
            qa[ks][3] = *(const unsigned*)(qbase + (size_t)(gr + 8) * 768 + 16 * ks + 2 * ci + 8);
        }
    }

    float Of[4][4];
    #pragma unroll
    for (int i = 0; i < 4; i++)
        #pragma unroll
        for (int j = 0; j < 4; j++) Of[i][j] = 0.f;
    float m0 = -1e30f, m1 = -1e30f, l0 = 0.f, l1 = 0.f;

    for (int j0 = 0; j0 < TT; j0 += 64) {
        __syncthreads();
        #pragma unroll
        for (int i = tid; i < 256; i += 128) {
            int r = i >> 2, w4 = i & 3;
            *(float4*)&Ks[r][w4 * 8] =
                *(const float4*)(g_qkvb + (size_t)(b * TT + j0 + r) * 768 + CC + h * HS + w4 * 8);
        }
        #pragma unroll
        for (int i = tid; i < 256; i += 128) {
            int d = i >> 3, c8 = i & 7;
            *(float4*)&Vt[d][c8 * 8] =
                *(const float4*)(g_vt + ((size_t)bh * HS + d) * TT + j0 + c8 * 8);
        }
        __syncthreads();

        float S[8][4];
        #pragma unroll
        for (int nt = 0; nt < 8; nt++)
            #pragma unroll
            for (int j = 0; j < 4; j++) S[nt][j] = 0.f;
        const unsigned* Ks32 = (const unsigned*)Ks;
        #pragma unroll
        for (int nt = 0; nt < 8; nt++) {
            int row = nt * 8 + gr;
            #pragma unroll
            for (int ks = 0; ks < 2; ks++) {
                unsigned b0 = Ks32[row * 20 + ks * 8 + ci];
                unsigned b1 = Ks32[row * 20 + ks * 8 + ci + 4];
                mma16816(S[nt], qa[ks][0], qa[ks][1], qa[ks][2], qa[ks][3], b0, b1);
            }
        }

        float cm0 = -1e30f, cm1 = -1e30f;
        #pragma unroll
        for (int nt = 0; nt < 8; nt++) {
            cm0 = fmaxf(cm0, fmaxf(S[nt][0], S[nt][1]));
            cm1 = fmaxf(cm1, fmaxf(S[nt][2], S[nt][3]));
        }
        cm0 = fmaxf(cm0, __shfl_xor_sync(0xffffffffu, cm0, 1));
        cm0 = fmaxf(cm0, __shfl_xor_sync(0xffffffffu, cm0, 2));
        cm1 = fmaxf(cm1, __shfl_xor_sync(0xffffffffu, cm1, 1));
        cm1 = fmaxf(cm1, __shfl_xor_sync(0xffffffffu, cm1, 2));
        float mn0 = fmaxf(m0, cm0);
        float mn1 = fmaxf(m1, cm1);
        float a0 = __expf(m0 - mn0);
        float a1 = __expf(m1 - mn1);
        m0 = mn0; m1 = mn1;
        l0 *= a0; l1 *= a1;
        #pragma unroll
        for (int nt = 0; nt < 4; nt++) {
            Of[nt][0] *= a0; Of[nt][1] *= a0;
            Of[nt][2] *= a1; Of[nt][3] *= a1;
        }

        unsigned pa[4][4];
        #pragma unroll
        for (int nt = 0; nt < 8; nt++) {
            float p0 = __expf(S[nt][0] - mn0);
            float p1 = __expf(S[nt][1] - mn0);
            float p2 = __expf(S[nt][2] - mn1);
            float p3 = __expf(S[nt][3] - mn1);
            l0 += p0 + p1;
            l1 += p2 + p3;
            __nv_bfloat162 lo = __float22bfloat162_rn(make_float2(p0, p1));
            __nv_bfloat162 hi = __float22bfloat162_rn(make_float2(p2, p3));
            int kk = nt >> 1, half = nt & 1;
            pa[kk][half * 2 + 0] = *(unsigned*)&lo;
            pa[kk][half * 2 + 1] = *(unsigned*)&hi;
        }

        const unsigned* Vt32 = (const unsigned*)Vt;
        #pragma unroll
        for (int kk = 0; kk < 4; kk++) {
            #pragma unroll
            for (int nt = 0; nt < 4; nt++) {
                int drow = nt * 8 + gr;
                unsigned b0 = Vt32[drow * 36 + kk * 8 + ci];
                unsigned b1 = Vt32[drow * 36 + kk * 8 + ci + 4];
                mma16816(Of[nt], pa[kk][0], pa[kk][1], pa[kk][2], pa[kk][3], b0, b1);
            }
        }
    }

    l0 += __shfl_xor_sync(0xffffffffu, l0, 1);
    l0 += __shfl_xor_sync(0xffffffffu, l0, 2);
    l1 += __shfl_xor_sync(0xffffffffu, l1, 1);
    l1 += __shfl_xor_sync(0xffffffffu, l1, 2);
    float i0 = 1.0f / l0;
    float i1 = 1.0f / l1;

    __nv_bfloat16* ob = g_ob + (size_t)(b * TT + t0 + w * 16) * CC + h * HS;
    #pragma unroll
    for (int nt = 0; nt < 4; nt++) {
        __nv_bfloat162 lo = __float22bfloat162_rn(make_float2(Of[nt][0] * i0, Of[nt][1] * i0));
        __nv_bfloat162 hi = __float22bfloat162_rn(make_float2(Of[nt][2] * i1, Of[nt][3] * i1));
        *(__nv_bfloat162*)(ob + (size_t)(gr)     * CC + nt * 8 + 2 * ci) = lo;
        *(__nv_bfloat162*)(ob + (size_t)(gr + 8) * CC + nt * 8 + 2 * ci) = hi;
    }
}

// ---------------- classifier (reads bf16 final LN) ---------------------------
__global__ void __launch_bounds__(1024) cls_kernel(
        const float* __restrict__ Wc1, const float* __restrict__ bc1,
        const float* __restrict__ Wc2, const float* __restrict__ bc2,
        float* __restrict__ out) {
    int b = blockIdx.x;
    int tid = threadIdx.x;
    __shared__ float emb4[4][CC];
    __shared__ float emb[CC];
    __shared__ float hid[CLS_H];
    __shared__ float lg[N_OUT];

    {
        int c   = tid & 255;
        int qtr = tid >> 8;
        float sum = 0.f;
        const __nv_bfloat16* base = g_hb + (size_t)b * TT * CC + (size_t)qtr * 512 * CC + c;
        for (int t = 0; t < 512; t++) sum += __bfloat162float(base[(size_t)t * CC]);
        emb4[qtr][c] = sum;
    }
    __syncthreads();
    if (tid < CC) {
        emb[tid] = (emb4[0][tid] + emb4[1][tid] + emb4[2][tid] + emb4[3][tid]) * (1.0f / TT);
    }
    __syncthreads();

    if (tid < CLS_H) {
        float sum = bc1[tid];
        for (int c = 0; c < CC; c++) sum += emb[c] * Wc1[(size_t)c * CLS_H + tid];
        hid[tid] = fmaxf(sum, 0.f);
    }
    __syncthreads();

    if (tid < N_OUT) {
        float sum = bc2[tid];
        for (int k = 0; k < CLS_H; k++) sum += hid[k] * Wc2[(size_t)k * N_OUT + tid];
        lg[tid] = sum;
    }
    __syncthreads();

    if (tid == 0) {
        float mx = lg[0];
        for (int j = 1; j < N_OUT; j++) mx = fmaxf(mx, lg[j]);
        float e[N_OUT], se = 0.f;
        for (int j = 0; j < N_OUT; j++) { e[j] = __expf(lg[j] - mx); se += e[j]; }
        float inv = 1.0f / se;
        for (int j = 0; j < N_OUT; j++) out[b * N_OUT + j] = e[j] * inv;
    }
}

// ---------------- launch ----------------------------------------------------
extern "C" void kernel_launch(void* const* d_in, const int* in_sizes, int n_in,
                              void* d_out, int out_size) {
    const int*   idx   = (const int*)  d_in[0];
    const float* tok   = (const float*)d_in[1];
    const float* pos   = (const float*)d_in[2];
    const float* Wq    = (const float*)d_in[3];
    const float* Wk    = (const float*)d_in[4];
    const float* Wv    = (const float*)d_in[5];
    const float* Wproj = (const float*)d_in[6];
    const float* bproj = (const float*)d_in[7];
    const float* ln1g  = (const float*)d_in[8];
    const float* ln1b  = (const float*)d_in[9];
    const float* ln2g  = (const float*)d_in[10];
    const float* ln2b  = (const float*)d_in[11];
    const float* W1    = (const float*)d_in[12];
    const float* b1    = (const float*)d_in[13];
    const float* W2    = (const float*)d_in[14];
    const float* b2    = (const float*)d_in[15];
    const float* lnfg  = (const float*)d_in[16];
    const float* lnfb  = (const float*)d_in[17];
    const float* Wc1   = (const float*)d_in[18];
    const float* bc1   = (const float*)d_in[19];
    const float* Wc2   = (const float*)d_in[20];
    const float* bc2   = (const float*)d_in[21];
    float* out = (float*)d_out;

    float* px;
    __nv_bfloat16 *phb, *pqkvb, *pob, *pfb, *pwqkvb, *pwprojb, *pw1b, *pw2b;
    cudaGetSymbolAddress((void**)&px,     g_x);
    cudaGetSymbolAddress((void**)&phb,    g_hb);
    cudaGetSymbolAddress((void**)&pqkvb,  g_qkvb);
    cudaGetSymbolAddress((void**)&pob,    g_ob);
    cudaGetSymbolAddress((void**)&pfb,    g_fb);
    cudaGetSymbolAddress((void**)&pwqkvb, g_wqkvb);
    cudaGetSymbolAddress((void**)&pwprojb,g_wprojb);
    cudaGetSymbolAddress((void**)&pw1b,   g_w1b);
    cudaGetSymbolAddress((void**)&pw2b,   g_w2b);

    embed_kernel<<<NTOK, CC>>>(idx, tok, pos);
    wconv_kernel<<<(WQKV_SZ + 3 * WSQ_SZ) / 256, 256>>>(Wq, Wk, Wv, Wproj, W1, W2);

    for (int l = 0; l < LL; l++) {
        ln_bf16_kernel<<<NTOK / 8, 256>>>(px, phb, ln1g + l * CC, ln1b + l * CC);
        // QKV: [8192,256]@[256,768] -> bf16 (q scaled)
        hgemm_kernel<0><<<dim3(768 / HGN, NTOK / HGM), 256>>>(
            phb, pwqkvb + (size_t)l * 768 * CC, pqkvb, nullptr, nullptr, NTOK, 768, CC);
        vtrans_kernel<<<dim3(TT / 64, BB * HH), 256>>>();
        attn_kernel<<<dim3(TT / 64, BB * HH), 128>>>();
        // proj + bias + residual -> x (fp32)
        hgemm_kernel<2><<<dim3(CC / HGN, NTOK / HGM), 256>>>(
            pob, pwprojb + (size_t)l * CC * CC, px, bproj + l * CC, px, NTOK, CC, CC);
        ln_bf16_kernel<<<NTOK / 8, 256>>>(px, phb, ln2g + l * CC, ln2b + l * CC);
        // FFN1: relu(h @ W1 + b1) -> bf16
        hgemm_kernel<3><<<dim3(FFN / HGN, NTOK / HGM), 256>>>(
            phb, pw1b + (size_t)l * CC * FFN, pfb, b1 + l * FFN, nullptr, NTOK, FFN, CC);
        // FFN2: x += f @ W2 + b2 (fp32)
        hgemm_kernel<2><<<dim3(CC / HGN, NTOK / HGM), 256>>>(
            pfb, pw2b + (size_t)l * FFN * CC, px, b2 + l * CC, px, NTOK, CC, FFN);
    }

    ln_bf16_kernel<<<NTOK / 8, 256>>>(px, phb, lnfg, lnfb);
    cls_kernel<<<BB, CLS_H * 2>>>(Wc1, bc1, Wc2, bc2, out);
}

// round 7
// speedup vs baseline: 31.9223x; 1.1371x over previous
#include <cuda_runtime.h>
#include <cuda_bf16.h>
#include <math.h>

// Problem constants
#define BB 4
#define TT 2048
#define CC 256
#define HH 8
#define HS 32
#define LL 4
#define FFN 256
#define CLS_H 512
#define N_OUT 10
#define NTOK (BB*TT)          // 8192

// ---------------- scratch (device globals; no allocations allowed) ----------
__device__ float g_x[NTOK*CC];                       // fp32 residual stream
__device__ __nv_bfloat16 g_hb  [NTOK*CC];            // bf16 LN output
__device__ __nv_bfloat16 g_qkvb[NTOK*3*CC];          // bf16 qkv (q pre-scaled 1/16)
__device__ __nv_bfloat16 g_ob  [NTOK*CC];            // bf16 attention output
__device__ __nv_bfloat16 g_fb  [NTOK*FFN];           // bf16 FFN hidden
__device__ __nv_bfloat16 g_wqkvb [LL*768*CC];        // [l][n][k] n=s*256+h*32+d
__device__ __nv_bfloat16 g_wprojb[LL*CC*CC];         // [l][n][k]
__device__ __nv_bfloat16 g_w1b   [LL*CC*FFN];
__device__ __nv_bfloat16 g_w2b   [LL*FFN*CC];
__device__ float g_pool[BB*32*CC];                   // partial mean-pool sums

// ---------------- asm helpers ------------------------------------------------
__device__ __forceinline__ unsigned scvt(const void* p) {
    return (unsigned)__cvta_generic_to_shared(p);
}
__device__ __forceinline__ void cp16(void* smem, const void* gmem) {
    asm volatile("cp.async.cg.shared.global [%0], [%1], 16;"
                 :: "r"(scvt(smem)), "l"(gmem));
}
#define CP_COMMIT() asm volatile("cp.async.commit_group;")
#define CP_WAIT1()  asm volatile("cp.async.wait_group 1;")
#define CP_WAIT0()  asm volatile("cp.async.wait_group 0;")

__device__ __forceinline__ void ldsm4(unsigned addr,
        unsigned &r0, unsigned &r1, unsigned &r2, unsigned &r3) {
    asm volatile("ldmatrix.sync.aligned.m8n8.x4.shared.b16 {%0,%1,%2,%3}, [%4];"
        : "=r"(r0), "=r"(r1), "=r"(r2), "=r"(r3) : "r"(addr));
}
__device__ __forceinline__ void ldsm4t(unsigned addr,
        unsigned &r0, unsigned &r1, unsigned &r2, unsigned &r3) {
    asm volatile("ldmatrix.sync.aligned.m8n8.x4.trans.shared.b16 {%0,%1,%2,%3}, [%4];"
        : "=r"(r0), "=r"(r1), "=r"(r2), "=r"(r3) : "r"(addr));
}
__device__ __forceinline__ void mma16816(float c[4],
        unsigned a0, unsigned a1, unsigned a2, unsigned a3,
        unsigned b0, unsigned b1) {
    asm volatile(
        "mma.sync.aligned.m16n8k16.row.col.f32.bf16.bf16.f32 "
        "{%0,%1,%2,%3}, {%4,%5,%6,%7}, {%8,%9}, {%0,%1,%2,%3};"
        : "+f"(c[0]), "+f"(c[1]), "+f"(c[2]), "+f"(c[3])
        : "r"(a0), "r"(a1), "r"(a2), "r"(a3), "r"(b0), "r"(b1));
}

// ---------------- embedding ------------------------------------------------
__global__ void embed_kernel(const int* __restrict__ idx,
                             const float* __restrict__ tok,
                             const float* __restrict__ pos) {
    int i = blockIdx.x;
    int c = threadIdx.x;
    int t = i & (TT - 1);
    g_x[(size_t)i * CC + c] = tok[(size_t)idx[i] * CC + c] + pos[(size_t)t * CC + c];
}

// ---------------- weight convert+transpose to bf16 ---------------------------
#define WQKV_SZ (LL*768*CC)
#define WSQ_SZ  (LL*CC*CC)
__global__ void wconv_kernel(const float* __restrict__ Wq, const float* __restrict__ Wk,
                             const float* __restrict__ Wv, const float* __restrict__ Wproj,
                             const float* __restrict__ W1, const float* __restrict__ W2) {
    int idx = blockIdx.x * 256 + threadIdx.x;
    if (idx < WQKV_SZ) {
        int k = idx & 255;
        int n = (idx >> 8) % 768;
        int l = idx / (768 * CC);
        int s = n >> 8, h = (n >> 5) & 7, d = n & 31;
        const float* W = (s == 0) ? Wq : (s == 1) ? Wk : Wv;
        g_wqkvb[idx] = __float2bfloat16(W[(((size_t)l * HH + h) * CC + k) * HS + d]);
    } else {
        int j = idx - WQKV_SZ;
        int seg = j / WSQ_SZ;
        int r = j % WSQ_SZ;
        int k = r & 255, n = (r >> 8) & 255, l = r >> 16;
        const float* W = (seg == 0) ? Wproj : (seg == 1) ? W1 : W2;
        float v = W[((size_t)l * CC + k) * CC + n];
        __nv_bfloat16* D = (seg == 0) ? g_wprojb : (seg == 1) ? g_w1b : g_w2b;
        D[r] = __float2bfloat16(v);
    }
}

// ---------------- LayerNorm: warp per token, bf16 out ------------------------
__global__ void __launch_bounds__(256) ln_bf16_kernel(
        const float* __restrict__ x, __nv_bfloat16* __restrict__ y,
        const float* __restrict__ g, const float* __restrict__ b) {
    int tokn = blockIdx.x * 8 + (threadIdx.x >> 5);
    int lane = threadIdx.x & 31;
    const float* xp = x + (size_t)tokn * CC + lane * 8;
    float4 v0 = *(const float4*)(xp);
    float4 v1 = *(const float4*)(xp + 4);
    float vv[8] = {v0.x, v0.y, v0.z, v0.w, v1.x, v1.y, v1.z, v1.w};

    float s = 0.f, s2 = 0.f;
    #pragma unroll
    for (int i = 0; i < 8; i++) { s += vv[i]; s2 += vv[i] * vv[i]; }
    #pragma unroll
    for (int o = 16; o > 0; o >>= 1) {
        s  += __shfl_xor_sync(0xffffffffu, s, o);
        s2 += __shfl_xor_sync(0xffffffffu, s2, o);
    }
    float mean = s * (1.0f / CC);
    float var  = s2 * (1.0f / CC) - mean * mean;
    float rstd = rsqrtf(var + 1e-5f);

    float4 g0 = *(const float4*)(g + lane * 8);
    float4 g1 = *(const float4*)(g + lane * 8 + 4);
    float4 b0 = *(const float4*)(b + lane * 8);
    float4 b1 = *(const float4*)(b + lane * 8 + 4);
    float gg[8] = {g0.x, g0.y, g0.z, g0.w, g1.x, g1.y, g1.z, g1.w};
    float bb[8] = {b0.x, b0.y, b0.z, b0.w, b1.x, b1.y, b1.z, b1.w};

    unsigned outp[4];
    #pragma unroll
    for (int p = 0; p < 4; p++) {
        __nv_bfloat162 h2 = __float22bfloat162_rn(make_float2(
            (vv[2*p+0] - mean) * rstd * gg[2*p+0] + bb[2*p+0],
            (vv[2*p+1] - mean) * rstd * gg[2*p+1] + bb[2*p+1]));
        outp[p] = *(unsigned*)&h2;
    }
    *(uint4*)(y + (size_t)tokn * CC + lane * 8) = make_uint4(outp[0], outp[1], outp[2], outp[3]);
}

// ---------------- bf16 HMMA GEMM, cp.async 2-stage, ldmatrix frags -----------
// C[M,N] = A[M,K] @ Bt[N,K]^T; K multiple of 32.
// EPI 0: bf16 store, cols<256 scaled by 1/16 (qkv)
// EPI 2: fp32 bias + residual in-place
// EPI 3: bf16 bias + relu
template <int EPI>
__global__ void __launch_bounds__(256) hgemm_kernel(
        const __nv_bfloat16* __restrict__ A, const __nv_bfloat16* __restrict__ Bt,
        void* __restrict__ Cout, const float* __restrict__ bias,
        float* __restrict__ res, int M, int N, int K) {
    __shared__ __nv_bfloat16 As[2][128][40];
    __shared__ __nv_bfloat16 Bs[2][64][40];

    int m0 = blockIdx.y * 128;
    int n0 = blockIdx.x * 64;
    int tid = threadIdx.x;
    int w = tid >> 5, lane = tid & 31;
    int wm = w >> 1, wn = w & 1;          // 4 x 2 warp grid
    int gr = lane >> 2, ci = lane & 3;
    int quad = lane >> 3, l7 = lane & 7;

    unsigned asBase = scvt(&As[0][0][0]);
    unsigned bsBase = scvt(&Bs[0][0][0]);
    const int ABUF = 128 * 40 * 2;
    const int BBUF = 64 * 40 * 2;

    // ldmatrix lane address components (elements)
    int rowA = wm * 32 + (quad & 1) * 8 + l7;      // + mt*16
    int colA = (quad >> 1) * 8;                    // + ks*16
    int rowB = wn * 32 + (quad >> 1) * 8 + l7;     // + ntp*16
    int colB = (quad & 1) * 8;                     // + ks*16

    float acc[2][4][4];
    #pragma unroll
    for (int mt = 0; mt < 2; mt++)
        #pragma unroll
        for (int nt = 0; nt < 4; nt++)
            #pragma unroll
            for (int r = 0; r < 4; r++) acc[mt][nt][r] = 0.f;

    auto loadT = [&](int buf, int k0) {
        #pragma unroll
        for (int i = 0; i < 2; i++) {
            int idx = tid + i * 256;
            int row = idx >> 2, j = idx & 3;
            cp16(&As[buf][row][j * 8], A + (size_t)(m0 + row) * K + k0 + j * 8);
        }
        {
            int row = tid >> 2, j = tid & 3;
            cp16(&Bs[buf][row][j * 8], Bt + (size_t)(n0 + row) * K + k0 + j * 8);
        }
    };

    int nk = K >> 5;
    loadT(0, 0); CP_COMMIT();
    for (int kt = 0; kt < nk; kt++) {
        if (kt + 1 < nk) { loadT((kt + 1) & 1, (kt + 1) * 32); CP_COMMIT(); CP_WAIT1(); }
        else             { CP_WAIT0(); }
        __syncthreads();

        unsigned ab = asBase + (kt & 1) * ABUF;
        unsigned bbse = bsBase + (kt & 1) * BBUF;
        #pragma unroll
        for (int ks = 0; ks < 2; ks++) {
            unsigned a[2][4];
            #pragma unroll
            for (int mt = 0; mt < 2; mt++)
                ldsm4(ab + (unsigned)(((rowA + mt * 16) * 40 + colA + ks * 16) * 2),
                      a[mt][0], a[mt][1], a[mt][2], a[mt][3]);
            unsigned bf[4][2];
            #pragma unroll
            for (int ntp = 0; ntp < 2; ntp++) {
                unsigned r0, r1, r2, r3;
                ldsm4(bbse + (unsigned)(((rowB + ntp * 16) * 40 + colB + ks * 16) * 2),
                      r0, r1, r2, r3);
                bf[ntp * 2][0] = r0; bf[ntp * 2][1] = r1;
                bf[ntp * 2 + 1][0] = r2; bf[ntp * 2 + 1][1] = r3;
            }
            #pragma unroll
            for (int mt = 0; mt < 2; mt++)
                #pragma unroll
                for (int nt = 0; nt < 4; nt++)
                    mma16816(acc[mt][nt], a[mt][0], a[mt][1], a[mt][2], a[mt][3],
                             bf[nt][0], bf[nt][1]);
        }
        __syncthreads();
    }

    // epilogue
    #pragma unroll
    for (int mt = 0; mt < 2; mt++) {
        int row0 = m0 + wm * 32 + mt * 16 + gr;
        int row1 = row0 + 8;
        #pragma unroll
        for (int nt = 0; nt < 4; nt++) {
            int col = n0 + wn * 32 + nt * 8 + 2 * ci;
            float c0 = acc[mt][nt][0], c1 = acc[mt][nt][1];
            float c2 = acc[mt][nt][2], c3 = acc[mt][nt][3];
            if (EPI == 0) {
                float qs = (n0 < 256) ? 0.0625f : 1.0f;
                __nv_bfloat16* C = (__nv_bfloat16*)Cout;
                __nv_bfloat162 lo = __float22bfloat162_rn(make_float2(c0 * qs, c1 * qs));
                __nv_bfloat162 hi = __float22bfloat162_rn(make_float2(c2 * qs, c3 * qs));
                *(__nv_bfloat162*)(C + (size_t)row0 * N + col) = lo;
                *(__nv_bfloat162*)(C + (size_t)row1 * N + col) = hi;
            } else if (EPI == 2) {
                float* C = (float*)Cout;
                float bz0 = bias[col], bz1 = bias[col + 1];
                float2 r0 = *(float2*)(res + (size_t)row0 * N + col);
                float2 r1 = *(float2*)(res + (size_t)row1 * N + col);
                *(float2*)(C + (size_t)row0 * N + col) = make_float2(c0 + bz0 + r0.x, c1 + bz1 + r0.y);
                *(float2*)(C + (size_t)row1 * N + col) = make_float2(c2 + bz0 + r1.x, c3 + bz1 + r1.y);
            } else {
                __nv_bfloat16* C = (__nv_bfloat16*)Cout;
                float bz0 = bias[col], bz1 = bias[col + 1];
                __nv_bfloat162 lo = __float22bfloat162_rn(make_float2(fmaxf(c0 + bz0, 0.f), fmaxf(c1 + bz1, 0.f)));
                __nv_bfloat162 hi = __float22bfloat162_rn(make_float2(fmaxf(c2 + bz0, 0.f), fmaxf(c3 + bz1, 0.f)));
                *(__nv_bfloat162*)(C + (size_t)row0 * N + col) = lo;
                *(__nv_bfloat162*)(C + (size_t)row1 * N + col) = hi;
            }
        }
    }
}

// ---------------- flash attention: HMMA + cp.async + ldmatrix ----------------
// grid (T/64, B*H), block 128 (4 warps). Warp w owns q rows [w*16, w*16+16).
__global__ void __launch_bounds__(128) attn_kernel(void) {
    int bh = blockIdx.y;
    int b = bh >> 3, h = bh & 7;
    int t0 = blockIdx.x * 64;

    __shared__ __nv_bfloat16 Ks[2][64][40];
    __shared__ __nv_bfloat16 Vs[2][64][40];

    int tid = threadIdx.x;
    int w = tid >> 5, lane = tid & 31;
    int gr = lane >> 2, ci = lane & 3;
    int quad = lane >> 3, l7 = lane & 7;

    unsigned ksBase = scvt(&Ks[0][0][0]);
    unsigned vsBase = scvt(&Vs[0][0][0]);
    const int TILEB = 64 * 40 * 2;

    int krow = (quad >> 1) * 8 + l7;     // + ntp*16
    int kcol = (quad & 1) * 8;           // + ks*16
    int vrow = (quad & 1) * 8 + l7;      // + kk*16
    int vcol = (quad >> 1) * 8;          // + db

    // Q fragments (bf16, pre-scaled 1/16)
    unsigned qa[2][4];
    {
        const __nv_bfloat16* qbase = g_qkvb + (size_t)(b * TT + t0 + w * 16) * 768 + h * HS;
        #pragma unroll
        for (int ks = 0; ks < 2; ks++) {
            qa[ks][0] = *(const unsigned*)(qbase + (size_t)(gr)     * 768 + 16 * ks + 2 * ci);
            qa[ks][1] = *(const unsigned*)(qbase + (size_t)(gr + 8) * 768 + 16 * ks + 2 * ci);
            qa[ks][2] = *(const unsigned*)(qbase + (size_t)(gr)     * 768 + 16 * ks + 2 * ci + 8);
            qa[ks][3] = *(const unsigned*)(qbase + (size_t)(gr + 8) * 768 + 16 * ks + 2 * ci + 8);
        }
    }

    auto loadKV = [&](int buf, int j0) {
        #pragma unroll
        for (int i = 0; i < 2; i++) {
            int idx = tid + i * 128;
            int r = idx >> 2, j = idx & 3;
            const __nv_bfloat16* base = g_qkvb + (size_t)(b * TT + j0 + r) * 768 + h * HS + j * 8;
            cp16(&Ks[buf][r][j * 8], base + 256);
            cp16(&Vs[buf][r][j * 8], base + 512);
        }
    };

    float Of[4][4];
    #pragma unroll
    for (int i = 0; i < 4; i++)
        #pragma unroll
        for (int j = 0; j < 4; j++) Of[i][j] = 0.f;
    float m0 = -1e30f, m1 = -1e30f, l0 = 0.f, l1 = 0.f;

    loadKV(0, 0); CP_COMMIT();
    for (int jt = 0; jt < TT / 64; jt++) {
        if (jt + 1 < TT / 64) { loadKV((jt + 1) & 1, (jt + 1) * 64); CP_COMMIT(); CP_WAIT1(); }
        else                  { CP_WAIT0(); }
        __syncthreads();

        unsigned kb0 = ksBase + (jt & 1) * TILEB;
        unsigned vb0 = vsBase + (jt & 1) * TILEB;

        // S = Q @ K^T
        float S[8][4];
        #pragma unroll
        for (int nt = 0; nt < 8; nt++)
            #pragma unroll
            for (int j = 0; j < 4; j++) S[nt][j] = 0.f;
        #pragma unroll
        for (int ks = 0; ks < 2; ks++) {
            unsigned kb[8][2];
            #pragma unroll
            for (int ntp = 0; ntp < 4; ntp++) {
                unsigned r0, r1, r2, r3;
                ldsm4(kb0 + (unsigned)(((ntp * 16 + krow) * 40 + kcol + ks * 16) * 2),
                      r0, r1, r2, r3);
                kb[ntp * 2][0] = r0; kb[ntp * 2][1] = r1;
                kb[ntp * 2 + 1][0] = r2; kb[ntp * 2 + 1][1] = r3;
            }
            #pragma unroll
            for (int nt = 0; nt < 8; nt++)
                mma16816(S[nt], qa[ks][0], qa[ks][1], qa[ks][2], qa[ks][3],
                         kb[nt][0], kb[nt][1]);
        }

        // online softmax in fragments
        float cm0 = -1e30f, cm1 = -1e30f;
        #pragma unroll
        for (int nt = 0; nt < 8; nt++) {
            cm0 = fmaxf(cm0, fmaxf(S[nt][0], S[nt][1]));
            cm1 = fmaxf(cm1, fmaxf(S[nt][2], S[nt][3]));
        }
        cm0 = fmaxf(cm0, __shfl_xor_sync(0xffffffffu, cm0, 1));
        cm0 = fmaxf(cm0, __shfl_xor_sync(0xffffffffu, cm0, 2));
        cm1 = fmaxf(cm1, __shfl_xor_sync(0xffffffffu, cm1, 1));
        cm1 = fmaxf(cm1, __shfl_xor_sync(0xffffffffu, cm1, 2));
        float mn0 = fmaxf(m0, cm0);
        float mn1 = fmaxf(m1, cm1);
        float a0 = __expf(m0 - mn0);
        float a1 = __expf(m1 - mn1);
        m0 = mn0; m1 = mn1;
        l0 *= a0; l1 *= a1;
        #pragma unroll
        for (int nt = 0; nt < 4; nt++) {
            Of[nt][0] *= a0; Of[nt][1] *= a0;
            Of[nt][2] *= a1; Of[nt][3] *= a1;
        }

        unsigned pa[4][4];
        #pragma unroll
        for (int nt = 0; nt < 8; nt++) {
            float p0 = __expf(S[nt][0] - mn0);
            float p1 = __expf(S[nt][1] - mn0);
            float p2 = __expf(S[nt][2] - mn1);
            float p3 = __expf(S[nt][3] - mn1);
            l0 += p0 + p1;
            l1 += p2 + p3;
            __nv_bfloat162 lo = __float22bfloat162_rn(make_float2(p0, p1));
            __nv_bfloat162 hi = __float22bfloat162_rn(make_float2(p2, p3));
            int kk = nt >> 1, half = nt & 1;
            pa[kk][half * 2 + 0] = *(unsigned*)&lo;
            pa[kk][half * 2 + 1] = *(unsigned*)&hi;
        }

        // O += P @ V via ldmatrix.trans B-frags
        #pragma unroll
        for (int kk = 0; kk < 4; kk++) {
            unsigned v0, v1, v2, v3, u0, u1, u2, u3;
            ldsm4t(vb0 + (unsigned)(((kk * 16 + vrow) * 40 + vcol) * 2),
                   v0, v1, v2, v3);
            ldsm4t(vb0 + (unsigned)(((kk * 16 + vrow) * 40 + vcol + 16) * 2),
                   u0, u1, u2, u3);
            mma16816(Of[0], pa[kk][0], pa[kk][1], pa[kk][2], pa[kk][3], v0, v1);
            mma16816(Of[1], pa[kk][0], pa[kk][1], pa[kk][2], pa[kk][3], v2, v3);
            mma16816(Of[2], pa[kk][0], pa[kk][1], pa[kk][2], pa[kk][3], u0, u1);
            mma16816(Of[3], pa[kk][0], pa[kk][1], pa[kk][2], pa[kk][3], u2, u3);
        }
        __syncthreads();
    }

    l0 += __shfl_xor_sync(0xffffffffu, l0, 1);
    l0 += __shfl_xor_sync(0xffffffffu, l0, 2);
    l1 += __shfl_xor_sync(0xffffffffu, l1, 1);
    l1 += __shfl_xor_sync(0xffffffffu, l1, 2);
    float i0 = 1.0f / l0;
    float i1 = 1.0f / l1;

    __nv_bfloat16* ob = g_ob + (size_t)(b * TT + t0 + w * 16) * CC + h * HS;
    #pragma unroll
    for (int nt = 0; nt < 4; nt++) {
        __nv_bfloat162 lo = __float22bfloat162_rn(make_float2(Of[nt][0] * i0, Of[nt][1] * i0));
        __nv_bfloat162 hi = __float22bfloat162_rn(make_float2(Of[nt][2] * i1, Of[nt][3] * i1));
        *(__nv_bfloat162*)(ob + (size_t)(gr)     * CC + nt * 8 + 2 * ci) = lo;
        *(__nv_bfloat162*)(ob + (size_t)(gr + 8) * CC + nt * 8 + 2 * ci) = hi;
    }
}

// ---------------- mean-pool partials (parallel) ------------------------------
__global__ void __launch_bounds__(256) pool_kernel(void) {
    int b = blockIdx.x >> 5, seg = blockIdx.x & 31;   // 64 rows per segment
    int w = threadIdx.x >> 5, lane = threadIdx.x & 31;
    __shared__ float sm[8][CC];

    float acc[8] = {0.f, 0.f, 0.f, 0.f, 0.f, 0.f, 0.f, 0.f};
    for (int r = w; r < 64; r += 8) {
        const __nv_bfloat16* p = g_hb + ((size_t)b * TT + seg * 64 + r) * CC + lane * 8;
        uint4 u = *(const uint4*)p;
        unsigned uu[4] = {u.x, u.y, u.z, u.w};
        #pragma unroll
        for (int i = 0; i < 4; i++) {
            __nv_bfloat162 h2 = *(__nv_bfloat162*)&uu[i];
            acc[2 * i + 0] += __bfloat162float(h2.x);
            acc[2 * i + 1] += __bfloat162float(h2.y);
        }
    }
    #pragma unroll
    for (int k = 0; k < 8; k++) sm[w][lane * 8 + k] = acc[k];
    __syncthreads();
    int c = threadIdx.x;
    float s = 0.f;
    #pragma unroll
    for (int w2 = 0; w2 < 8; w2++) s += sm[w2][c];
    g_pool[((size_t)b * 32 + seg) * CC + c] = s;
}

// ---------------- classifier ------------------------------------------------
__global__ void __launch_bounds__(512) cls_kernel(
        const float* __restrict__ Wc1, const float* __restrict__ bc1,
        const float* __restrict__ Wc2, const float* __restrict__ bc2,
        float* __restrict__ out) {
    int b = blockIdx.x;
    int tid = threadIdx.x;
    __shared__ float emb[CC];
    __shared__ float hid[CLS_H];
    __shared__ float lg[N_OUT];

    if (tid < CC) {
        float s = 0.f;
        #pragma unroll
        for (int seg = 0; seg < 32; seg++) s += g_pool[((size_t)b * 32 + seg) * CC + tid];
        emb[tid] = s * (1.0f / TT);
    }
    __syncthreads();

    {
        float sum = bc1[tid];
        for (int c = 0; c < CC; c++) sum += emb[c] * Wc1[(size_t)c * CLS_H + tid];
        hid[tid] = fmaxf(sum, 0.f);
    }
    __syncthreads();

    if (tid < N_OUT) {
        float sum = bc2[tid];
        for (int k = 0; k < CLS_H; k++) sum += hid[k] * Wc2[(size_t)k * N_OUT + tid];
        lg[tid] = sum;
    }
    __syncthreads();

    if (tid == 0) {
        float mx = lg[0];
        for (int j = 1; j < N_OUT; j++) mx = fmaxf(mx, lg[j]);
        float e[N_OUT], se = 0.f;
        for (int j = 0; j < N_OUT; j++) { e[j] = __expf(lg[j] - mx); se += e[j]; }
        float inv = 1.0f / se;
        for (int j = 0; j < N_OUT; j++) out[b * N_OUT + j] = e[j] * inv;
    }
}

// ---------------- launch ----------------------------------------------------
extern "C" void kernel_launch(void* const* d_in, const int* in_sizes, int n_in,
                              void* d_out, int out_size) {
    const int*   idx   = (const int*)  d_in[0];
    const float* tok   = (const float*)d_in[1];
    const float* pos   = (const float*)d_in[2];
    const float* Wq    = (const float*)d_in[3];
    const float* Wk    = (const float*)d_in[4];
    const float* Wv    = (const float*)d_in[5];
    const float* Wproj = (const float*)d_in[6];
    const float* bproj = (const float*)d_in[7];
    const float* ln1g  = (const float*)d_in[8];
    const float* ln1b  = (const float*)d_in[9];
    const float* ln2g  = (const float*)d_in[10];
    const float* ln2b  = (const float*)d_in[11];
    const float* W1    = (const float*)d_in[12];
    const float* b1    = (const float*)d_in[13];
    const float* W2    = (const float*)d_in[14];
    const float* b2    = (const float*)d_in[15];
    const float* lnfg  = (const float*)d_in[16];
    const float* lnfb  = (const float*)d_in[17];
    const float* Wc1   = (const float*)d_in[18];
    const float* bc1   = (const float*)d_in[19];
    const float* Wc2   = (const float*)d_in[20];
    const float* bc2   = (const float*)d_in[21];
    float* out = (float*)d_out;

    float* px;
    __nv_bfloat16 *phb, *pqkvb, *pob, *pfb, *pwqkvb, *pwprojb, *pw1b, *pw2b;
    cudaGetSymbolAddress((void**)&px,     g_x);
    cudaGetSymbolAddress((void**)&phb,    g_hb);
    cudaGetSymbolAddress((void**)&pqkvb,  g_qkvb);
    cudaGetSymbolAddress((void**)&pob,    g_ob);
    cudaGetSymbolAddress((void**)&pfb,    g_fb);
    cudaGetSymbolAddress((void**)&pwqkvb, g_wqkvb);
    cudaGetSymbolAddress((void**)&pwprojb,g_wprojb);
    cudaGetSymbolAddress((void**)&pw1b,   g_w1b);
    cudaGetSymbolAddress((void**)&pw2b,   g_w2b);

    embed_kernel<<<NTOK, CC>>>(idx, tok, pos);
    wconv_kernel<<<(WQKV_SZ + 3 * WSQ_SZ) / 256, 256>>>(Wq, Wk, Wv, Wproj, W1, W2);

    for (int l = 0; l < LL; l++) {
        ln_bf16_kernel<<<NTOK / 8, 256>>>(px, phb, ln1g + l * CC, ln1b + l * CC);
        // QKV: [8192,256]@[256,768] -> bf16 (q scaled)
        hgemm_kernel<0><<<dim3(768 / 64, NTOK / 128), 256>>>(
            phb, pwqkvb + (size_t)l * 768 * CC, pqkvb, nullptr, nullptr, NTOK, 768, CC);
        attn_kernel<<<dim3(TT / 64, BB * HH), 128>>>();
        // proj + bias + residual -> x (fp32)
        hgemm_kernel<2><<<dim3(CC / 64, NTOK / 128), 256>>>(
            pob, pwprojb + (size_t)l * CC * CC, px, bproj + l * CC, px, NTOK, CC, CC);
        ln_bf16_kernel<<<NTOK / 8, 256>>>(px, phb, ln2g + l * CC, ln2b + l * CC);
        // FFN1: relu(h @ W1 + b1) -> bf16
        hgemm_kernel<3><<<dim3(FFN / 64, NTOK / 128), 256>>>(
            phb, pw1b + (size_t)l * CC * FFN, pfb, b1 + l * FFN, nullptr, NTOK, FFN, CC);
        // FFN2: x += f @ W2 + b2 (fp32)
        hgemm_kernel<2><<<dim3(CC / 64, NTOK / 128), 256>>>(
            pfb, pw2b + (size_t)l * FFN * CC, px, b2 + l * CC, px, NTOK, CC, FFN);
    }

    ln_bf16_kernel<<<NTOK / 8, 256>>>(px, phb, lnfg, lnfb);
    pool_kernel<<<BB * 32, 256>>>();
    cls_kernel<<<BB, CLS_H>>>(Wc1, bc1, Wc2, bc2, out);
}